// round 1
// baseline (speedup 1.0000x reference)
#include <cuda_runtime.h>
#include <cstdint>
#include <cstddef>

#define B_   32
#define T_   512
#define H_   512
#define D_   512
#define SIXH 3072
#define BH   (B_ * H_)

#define NBLK 128       // persistent blocks (<= #SMs, 1 block/SM by smem)
#define JPB  4         // h-columns (j0) per block: 128*4 = 512 = H
#define NROW 20        // 5 gates * JPB Ws rows per block
#define WSTR 520       // padded Ws row stride in smem (bank-conflict-free)
#define NTHR 256

// Scratch (device globals: allocation-free per harness rules)
__device__ float    g_pi[(size_t)B_ * T_ * SIXH];   // 201 MB input projections
__device__ float    g_h[2 * BH];                    // double-buffered hidden state
__device__ unsigned g_bar;                          // monotonic grid barrier

__global__ void init_k() { g_bar = 0u; }

// ---------------------------------------------------------------------------
// GEMM: g_pi[m][n] = sum_k x[m][k] * Wi[n][k] + bi[n]
// M=16384, N=3072, K=512. 128x128 block tile, 8x8 per thread, K-tile 16.
// ---------------------------------------------------------------------------
__global__ __launch_bounds__(256) void gemm_pi_k(const float* __restrict__ A,
                                                 const float* __restrict__ W,
                                                 const float* __restrict__ bi) {
    __shared__ float As[16][128];
    __shared__ float Bs[16][128];
    const int tid  = threadIdx.x;
    const int m0   = blockIdx.y * 128;
    const int n0   = blockIdx.x * 128;
    const int lrow = tid & 127;         // 0..127 : tile row loaded by this thread
    const int lk   = (tid >> 7) * 8;    // 0 or 8 : k-offset half
    const float* Ap = A + (size_t)(m0 + lrow) * D_ + lk;
    const float* Wp = W + (size_t)(n0 + lrow) * D_ + lk;
    const int tx = tid & 15;
    const int ty = tid >> 4;

    float acc[8][8];
#pragma unroll
    for (int i = 0; i < 8; i++)
#pragma unroll
        for (int j = 0; j < 8; j++) acc[i][j] = 0.f;

    for (int kt = 0; kt < D_; kt += 16) {
        float4 a0 = *(const float4*)(Ap + kt);
        float4 a1 = *(const float4*)(Ap + kt + 4);
        float4 w0 = *(const float4*)(Wp + kt);
        float4 w1 = *(const float4*)(Wp + kt + 4);
        __syncthreads();
        As[lk + 0][lrow] = a0.x; As[lk + 1][lrow] = a0.y;
        As[lk + 2][lrow] = a0.z; As[lk + 3][lrow] = a0.w;
        As[lk + 4][lrow] = a1.x; As[lk + 5][lrow] = a1.y;
        As[lk + 6][lrow] = a1.z; As[lk + 7][lrow] = a1.w;
        Bs[lk + 0][lrow] = w0.x; Bs[lk + 1][lrow] = w0.y;
        Bs[lk + 2][lrow] = w0.z; Bs[lk + 3][lrow] = w0.w;
        Bs[lk + 4][lrow] = w1.x; Bs[lk + 5][lrow] = w1.y;
        Bs[lk + 6][lrow] = w1.z; Bs[lk + 7][lrow] = w1.w;
        __syncthreads();
#pragma unroll
        for (int k = 0; k < 16; k++) {
            float4 af0 = *(const float4*)&As[k][ty * 8];
            float4 af1 = *(const float4*)&As[k][ty * 8 + 4];
            float4 bf0 = *(const float4*)&Bs[k][tx * 8];
            float4 bf1 = *(const float4*)&Bs[k][tx * 8 + 4];
            float av[8] = {af0.x, af0.y, af0.z, af0.w, af1.x, af1.y, af1.z, af1.w};
            float bv[8] = {bf0.x, bf0.y, bf0.z, bf0.w, bf1.x, bf1.y, bf1.z, bf1.w};
#pragma unroll
            for (int i = 0; i < 8; i++)
#pragma unroll
                for (int j = 0; j < 8; j++) acc[i][j] += av[i] * bv[j];
        }
    }

    float bb[8];
#pragma unroll
    for (int j = 0; j < 8; j++) bb[j] = bi[n0 + tx * 8 + j];
#pragma unroll
    for (int i = 0; i < 8; i++) {
        float* C = g_pi + (size_t)(m0 + ty * 8 + i) * SIXH + n0 + tx * 8;
        float4 r0 = make_float4(acc[i][0] + bb[0], acc[i][1] + bb[1],
                                acc[i][2] + bb[2], acc[i][3] + bb[3]);
        float4 r1 = make_float4(acc[i][4] + bb[4], acc[i][5] + bb[5],
                                acc[i][6] + bb[6], acc[i][7] + bb[7]);
        *(float4*)C = r0;
        *(float4*)(C + 4) = r1;
    }
}

// ---------------------------------------------------------------------------
// Persistent recurrent scan.
// Block `blk` owns j0 in [blk*4, blk*4+4) and the 20 Ws rows {g*H + j0}.
// Per step: all blocks copy full h (64KB) to smem, compute their 32x20 dot
// block (K=512) with a 4b x 5r register tile, reduce over the 8-way d-split
// via shuffles, apply gates (c lives in registers), write h slice, barrier.
// ---------------------------------------------------------------------------
__device__ __forceinline__ float sigm(float x)  { return 1.f / (1.f + __expf(-x)); }
__device__ __forceinline__ float tanh_(float x) { return 1.f - 2.f / (__expf(2.f * x) + 1.f); }

__global__ __launch_bounds__(NTHR, 1) void lstm_scan_k(
    const float* __restrict__ Ws, const float* __restrict__ bs,
    const int* __restrict__ lengths, float* __restrict__ out)
{
    extern __shared__ float sm[];
    float* sWs  = sm;                    // NROW * WSTR   (41.6 KB)
    float* sH   = sm + NROW * WSTR;      // B_ * H_       (64 KB)
    float* sRed = sH + BH;               // B_ * NROW     (2.5 KB)

    const int tid = threadIdx.x;
    const int blk = blockIdx.x;
    const int td  = tid & 7;             // d-slice   (8)
    const int tr  = (tid >> 3) & 3;      // row group (4 groups of 5)
    const int tb  = tid >> 5;            // b group   (8 groups of 4)

    // Load this block's 20 Ws rows into smem (resident for all 512 steps).
    // Local row l maps to Ws row (l>>2)*H + blk*4 + (l&3)  [l = g*4 + jj].
    for (int i = tid; i < NROW * (H_ / 4); i += NTHR) {
        int l   = i >> 7;                // H_/4 = 128 vec4 per row
        int d4  = (i & 127) << 2;
        int row = (l >> 2) * H_ + blk * JPB + (l & 3);
        float4 v = *(const float4*)(Ws + (size_t)row * H_ + d4);
        float* p = sWs + l * WSTR + d4;
        p[0] = v.x; p[1] = v.y; p[2] = v.z; p[3] = v.w;
    }

    // Gate threads: tid<128 owns (b = tid>>2, jj = tid&3). c stays in register.
    float c_reg = 0.f;
    float bsv[5] = {0.f, 0.f, 0.f, 0.f, 0.f};
    int bg = 0, j0 = 0, len = 0;
    if (tid < 128) {
        bg = tid >> 2;
        j0 = blk * JPB + (tid & 3);
        len = lengths[bg];
#pragma unroll
        for (int g = 0; g < 5; g++) bsv[g] = bs[g * H_ + j0];
        __stcg(&g_h[bg * H_ + j0], 0.f);          // h0 = 0 (buffer 0)
    }
    __threadfence();
    __syncthreads();
    unsigned epoch = 1;
    if (tid == 0) {
        atomicAdd(&g_bar, 1u);
        while (*(volatile unsigned*)&g_bar < NBLK * epoch) {}
    }
    __syncthreads();

    for (int t = 0; t < T_; t++) {
        // Prefetch this step's pi values (6 per gate thread) early.
        float piv[6] = {0.f, 0.f, 0.f, 0.f, 0.f, 0.f};
        if (tid < 128) {
            const float* pp = g_pi + ((size_t)bg * T_ + t) * SIXH + j0;
#pragma unroll
            for (int g = 0; g < 6; g++) piv[g] = __ldg(pp + g * H_);
        }

        // Copy full h (read buffer t&1) into smem; L2 is the coherence point.
        const float4* hsrc = (const float4*)(g_h + (t & 1) * BH);
        for (int i = tid; i < BH / 4; i += NTHR)
            ((float4*)sH)[i] = __ldcg(hsrc + i);
        __syncthreads();

        // Dot phase: acc[4 b][5 rows] over 64 d-values (d = td + 8k).
        float acc[4][5];
#pragma unroll
        for (int q = 0; q < 4; q++)
#pragma unroll
            for (int r = 0; r < 5; r++) acc[q][r] = 0.f;

        const float* hp = sH + (tb * 4) * H_ + td;
        const float* wp = sWs + (tr * 5) * WSTR + td;
#pragma unroll 4
        for (int k = 0; k < 64; k++) {
            const int d = k << 3;
            float hv[4], wv[5];
#pragma unroll
            for (int q = 0; q < 4; q++) hv[q] = hp[q * H_ + d];
#pragma unroll
            for (int r = 0; r < 5; r++) wv[r] = wp[r * WSTR + d];
#pragma unroll
            for (int q = 0; q < 4; q++)
#pragma unroll
                for (int r = 0; r < 5; r++) acc[q][r] += hv[q] * wv[r];
        }

        // Reduce the 8-way d-split (lanes differing only in td) via shuffles.
#pragma unroll
        for (int q = 0; q < 4; q++)
#pragma unroll
            for (int r = 0; r < 5; r++) {
                float v = acc[q][r];
                v += __shfl_xor_sync(0xffffffffu, v, 1);
                v += __shfl_xor_sync(0xffffffffu, v, 2);
                v += __shfl_xor_sync(0xffffffffu, v, 4);
                if (td == 0) sRed[(tb * 4 + q) * NROW + tr * 5 + r] = v;
            }
        __syncthreads();

        // Gate phase.
        if (tid < 128) {
            const int jj = tid & 3;
            const float* rb = sRed + bg * NROW + jj;    // rb[g*4] = ps gate g
            float ps0 = rb[0]  + bsv[0];
            float ps1 = rb[4]  + bsv[1];
            float ps2 = rb[8]  + bsv[2];
            float ps3 = rb[12] + bsv[3];
            float ps4 = rb[16] + bsv[4];
            float iv = sigm(piv[0] + ps0);
            float fv = sigm(piv[1] + ps1);
            float gv = tanh_(piv[2] + ps2);
            float ov = sigm(piv[3] + ps3);
            float cn = iv * gv + fv * c_reg;
            float o1 = ov * tanh_(cn);
            float rv = sigm(piv[4] + ps4);
            float o2 = rv * o1 + (1.f - rv) * piv[5];
            bool  m  = (t < len);
            float hprev = sH[bg * H_ + j0];
            float hn = m ? o2 : hprev;
            c_reg    = m ? cn : c_reg;
            __stcg(&g_h[((t + 1) & 1) * BH + bg * H_ + j0], hn);
            out[((size_t)bg * T_ + t) * H_ + j0] = m ? o2 : 0.f;
            if (t == T_ - 1) {
                out[(size_t)B_ * T_ * H_ + bg * H_ + j0]      = hn;   // hT
                out[(size_t)B_ * T_ * H_ + BH + bg * H_ + j0] = c_reg; // cT
            }
        }

        // Grid barrier (monotonic counter; release via per-thread fence).
        __threadfence();
        __syncthreads();
        epoch++;
        if (tid == 0) {
            atomicAdd(&g_bar, 1u);
            while (*(volatile unsigned*)&g_bar < NBLK * epoch) {}
        }
        __syncthreads();
    }
}

// ---------------------------------------------------------------------------
extern "C" void kernel_launch(void* const* d_in, const int* in_sizes, int n_in,
                              void* d_out, int out_size) {
    const float* x       = (const float*)d_in[0];
    const int*   lengths = (const int*)  d_in[1];
    const float* Wi      = (const float*)d_in[2];
    const float* bi      = (const float*)d_in[3];
    const float* Ws      = (const float*)d_in[4];
    const float* bs      = (const float*)d_in[5];
    float* out = (float*)d_out;

    const int smem = (NROW * WSTR + BH + B_ * NROW) * (int)sizeof(float); // 109,696 B
    cudaFuncSetAttribute(lstm_scan_k, cudaFuncAttributeMaxDynamicSharedMemorySize, smem);

    init_k<<<1, 1>>>();
    gemm_pi_k<<<dim3(SIXH / 128, (B_ * T_) / 128), 256>>>(x, Wi, bi);
    lstm_scan_k<<<NBLK, NTHR, smem>>>(Ws, bs, lengths, out);
}

// round 2
// speedup vs baseline: 1.1881x; 1.1881x over previous
#include <cuda_runtime.h>
#include <cuda_bf16.h>
#include <cstdint>
#include <cstddef>

#define B_   32
#define T_   512
#define H_   512
#define D_   512
#define SIXH 3072
#define BH   (B_ * H_)

#define NBLK 128
#define JPB  4
#define NROW 20
#define WSTR 520
#define NTHR 256

// Scratch (device globals: allocation-free per harness rules)
__device__ float         g_pi[(size_t)B_ * T_ * SIXH];    // 201 MB
__device__ float         g_h[2 * BH];
__device__ unsigned      g_bar;
__device__ __nv_bfloat16 g_xhi[(size_t)B_ * T_ * D_];
__device__ __nv_bfloat16 g_xlo[(size_t)B_ * T_ * D_];
__device__ __nv_bfloat16 g_whi[(size_t)SIXH * D_];
__device__ __nv_bfloat16 g_wlo[(size_t)SIXH * D_];

__global__ void init_k() { g_bar = 0u; }

// ---------------------------------------------------------------------------
// fp32 -> (bf16 hi, bf16 lo) split
// ---------------------------------------------------------------------------
__global__ void split_k(const float* __restrict__ src,
                        __nv_bfloat16* __restrict__ hi,
                        __nv_bfloat16* __restrict__ lo, int n4) {
    int i = blockIdx.x * blockDim.x + threadIdx.x;
    if (i >= n4) return;
    float4 f = ((const float4*)src)[i];
    __nv_bfloat16 h0 = __float2bfloat16(f.x);
    __nv_bfloat16 h1 = __float2bfloat16(f.y);
    __nv_bfloat16 h2 = __float2bfloat16(f.z);
    __nv_bfloat16 h3 = __float2bfloat16(f.w);
    __nv_bfloat162 hv0, hv1, lv0, lv1;
    hv0.x = h0; hv0.y = h1; hv1.x = h2; hv1.y = h3;
    lv0.x = __float2bfloat16(f.x - __bfloat162float(h0));
    lv0.y = __float2bfloat16(f.y - __bfloat162float(h1));
    lv1.x = __float2bfloat16(f.z - __bfloat162float(h2));
    lv1.y = __float2bfloat16(f.w - __bfloat162float(h3));
    ((__nv_bfloat162*)hi)[2 * i]     = hv0;
    ((__nv_bfloat162*)hi)[2 * i + 1] = hv1;
    ((__nv_bfloat162*)lo)[2 * i]     = lv0;
    ((__nv_bfloat162*)lo)[2 * i + 1] = lv1;
}

// ---------------------------------------------------------------------------
// Tensor-core GEMM: g_pi[m][n] = sum_k x[m][k]*Wi[n][k] + bi[n]
// bf16 3-term split (hi*hi + hi*lo + lo*hi), mma.sync m16n8k16.
// 128x128 block tile, 8 warps (2m x 4n), warp tile 64x32, k-tile 16.
// ---------------------------------------------------------------------------
__device__ __forceinline__ void ldsm_x4(uint32_t& r0, uint32_t& r1,
                                        uint32_t& r2, uint32_t& r3, uint32_t a) {
    asm volatile("ldmatrix.sync.aligned.m8n8.x4.shared.b16 {%0,%1,%2,%3}, [%4];"
                 : "=r"(r0), "=r"(r1), "=r"(r2), "=r"(r3) : "r"(a));
}
__device__ __forceinline__ void mma16816(float* c, const uint32_t* a,
                                         uint32_t b0, uint32_t b1) {
    asm volatile(
        "mma.sync.aligned.m16n8k16.row.col.f32.bf16.bf16.f32 "
        "{%0,%1,%2,%3},{%4,%5,%6,%7},{%8,%9},{%0,%1,%2,%3};"
        : "+f"(c[0]), "+f"(c[1]), "+f"(c[2]), "+f"(c[3])
        : "r"(a[0]), "r"(a[1]), "r"(a[2]), "r"(a[3]), "r"(b0), "r"(b1));
}

#define ASTR 48   // bytes per 16-bf16 row (32B data + 16B pad, conflict-free)

__global__ __launch_bounds__(256) void gemm_pi_mma_k(const float* __restrict__ bi) {
    __shared__ char smem[4 * 128 * ASTR];   // Ahi, Alo, Bhi, Blo (6 KB each)
    char* sAhi = smem;
    char* sAlo = smem + 128 * ASTR;
    char* sBhi = smem + 2 * 128 * ASTR;
    char* sBlo = smem + 3 * 128 * ASTR;

    const int tid  = threadIdx.x;
    const int lane = tid & 31;
    const int warp = tid >> 5;
    const int wm   = warp >> 2;          // 0..1
    const int wn   = warp & 3;           // 0..3
    const int m0   = blockIdx.y * 128;
    const int n0   = blockIdx.x * 128;

    const int lrow = tid >> 1;           // 0..127
    const int lhalf = tid & 1;           // which 8-bf16 half of the 16-k row
    const __nv_bfloat16* pxh = g_xhi + (size_t)(m0 + lrow) * D_ + lhalf * 8;
    const __nv_bfloat16* pxl = g_xlo + (size_t)(m0 + lrow) * D_ + lhalf * 8;
    const __nv_bfloat16* pwh = g_whi + (size_t)(n0 + lrow) * D_ + lhalf * 8;
    const __nv_bfloat16* pwl = g_wlo + (size_t)(n0 + lrow) * D_ + lhalf * 8;
    char* stA_hi = sAhi + lrow * ASTR + lhalf * 16;
    char* stA_lo = sAlo + lrow * ASTR + lhalf * 16;
    char* stB_hi = sBhi + lrow * ASTR + lhalf * 16;
    char* stB_lo = sBlo + lrow * ASTR + lhalf * 16;

    // ldmatrix source addresses (shared-space u32)
    const int rowA = wm * 64 + (lane & 15);
    const uint32_t aAh = (uint32_t)__cvta_generic_to_shared(
        sAhi + rowA * ASTR + (lane >> 4) * 16);
    const uint32_t aAl = aAh + 128 * ASTR;
    const int rowB = wn * 32 + (lane & 7) + ((lane >> 4) << 3);
    const uint32_t aBh = (uint32_t)__cvta_generic_to_shared(
        sBhi + rowB * ASTR + ((lane >> 3) & 1) * 16);
    const uint32_t aBl = aBh + 128 * ASTR;

    float acc[4][4][4];
#pragma unroll
    for (int i = 0; i < 4; i++)
#pragma unroll
        for (int j = 0; j < 4; j++)
#pragma unroll
            for (int e = 0; e < 4; e++) acc[i][j][e] = 0.f;

    uint4 rxh = *(const uint4*)pxh;
    uint4 rxl = *(const uint4*)pxl;
    uint4 rwh = *(const uint4*)pwh;
    uint4 rwl = *(const uint4*)pwl;

    for (int kt = 0; kt < D_; kt += 16) {
        __syncthreads();
        *(uint4*)stA_hi = rxh;
        *(uint4*)stA_lo = rxl;
        *(uint4*)stB_hi = rwh;
        *(uint4*)stB_lo = rwl;
        __syncthreads();
        if (kt + 16 < D_) {
            rxh = *(const uint4*)(pxh + kt + 16);
            rxl = *(const uint4*)(pxl + kt + 16);
            rwh = *(const uint4*)(pwh + kt + 16);
            rwl = *(const uint4*)(pwl + kt + 16);
        }

        uint32_t ah[4][4], al[4][4], bh[4][2], bl[4][2];
#pragma unroll
        for (int mi = 0; mi < 4; mi++) {
            ldsm_x4(ah[mi][0], ah[mi][1], ah[mi][2], ah[mi][3], aAh + mi * 16 * ASTR);
            ldsm_x4(al[mi][0], al[mi][1], al[mi][2], al[mi][3], aAl + mi * 16 * ASTR);
        }
#pragma unroll
        for (int bg = 0; bg < 2; bg++) {
            ldsm_x4(bh[2 * bg][0], bh[2 * bg][1], bh[2 * bg + 1][0], bh[2 * bg + 1][1],
                    aBh + bg * 16 * ASTR);
            ldsm_x4(bl[2 * bg][0], bl[2 * bg][1], bl[2 * bg + 1][0], bl[2 * bg + 1][1],
                    aBl + bg * 16 * ASTR);
        }
#pragma unroll
        for (int mi = 0; mi < 4; mi++)
#pragma unroll
            for (int ni = 0; ni < 4; ni++) {
                mma16816(acc[mi][ni], ah[mi], bh[ni][0], bh[ni][1]);
                mma16816(acc[mi][ni], ah[mi], bl[ni][0], bl[ni][1]);
                mma16816(acc[mi][ni], al[mi], bh[ni][0], bh[ni][1]);
            }
    }

    // Epilogue: bias + store
#pragma unroll
    for (int ni = 0; ni < 4; ni++) {
        const int n = n0 + wn * 32 + ni * 8 + 2 * (lane & 3);
        float b0 = bi[n], b1 = bi[n + 1];
#pragma unroll
        for (int mi = 0; mi < 4; mi++) {
            const int m = m0 + wm * 64 + mi * 16 + (lane >> 2);
            float* C0 = g_pi + (size_t)m * SIXH + n;
            float* C1 = g_pi + (size_t)(m + 8) * SIXH + n;
            *(float2*)C0 = make_float2(acc[mi][ni][0] + b0, acc[mi][ni][1] + b1);
            *(float2*)C1 = make_float2(acc[mi][ni][2] + b0, acc[mi][ni][3] + b1);
        }
    }
}

// ---------------------------------------------------------------------------
// Persistent recurrent scan (unchanged from Round 1).
// ---------------------------------------------------------------------------
__device__ __forceinline__ float sigm(float x)  { return 1.f / (1.f + __expf(-x)); }
__device__ __forceinline__ float tanh_(float x) { return 1.f - 2.f / (__expf(2.f * x) + 1.f); }

__global__ __launch_bounds__(NTHR, 1) void lstm_scan_k(
    const float* __restrict__ Ws, const float* __restrict__ bs,
    const int* __restrict__ lengths, float* __restrict__ out)
{
    extern __shared__ float sm[];
    float* sWs  = sm;
    float* sH   = sm + NROW * WSTR;
    float* sRed = sH + BH;

    const int tid = threadIdx.x;
    const int blk = blockIdx.x;
    const int td  = tid & 7;
    const int tr  = (tid >> 3) & 3;
    const int tb  = tid >> 5;

    for (int i = tid; i < NROW * (H_ / 4); i += NTHR) {
        int l   = i >> 7;
        int d4  = (i & 127) << 2;
        int row = (l >> 2) * H_ + blk * JPB + (l & 3);
        float4 v = *(const float4*)(Ws + (size_t)row * H_ + d4);
        float* p = sWs + l * WSTR + d4;
        p[0] = v.x; p[1] = v.y; p[2] = v.z; p[3] = v.w;
    }

    float c_reg = 0.f;
    float bsv[5] = {0.f, 0.f, 0.f, 0.f, 0.f};
    int bg = 0, j0 = 0, len = 0;
    if (tid < 128) {
        bg = tid >> 2;
        j0 = blk * JPB + (tid & 3);
        len = lengths[bg];
#pragma unroll
        for (int g = 0; g < 5; g++) bsv[g] = bs[g * H_ + j0];
        __stcg(&g_h[bg * H_ + j0], 0.f);
    }
    __threadfence();
    __syncthreads();
    unsigned epoch = 1;
    if (tid == 0) {
        atomicAdd(&g_bar, 1u);
        while (*(volatile unsigned*)&g_bar < NBLK * epoch) {}
    }
    __syncthreads();

    for (int t = 0; t < T_; t++) {
        float piv[6] = {0.f, 0.f, 0.f, 0.f, 0.f, 0.f};
        if (tid < 128) {
            const float* pp = g_pi + ((size_t)bg * T_ + t) * SIXH + j0;
#pragma unroll
            for (int g = 0; g < 6; g++) piv[g] = __ldg(pp + g * H_);
        }

        const float4* hsrc = (const float4*)(g_h + (t & 1) * BH);
        for (int i = tid; i < BH / 4; i += NTHR)
            ((float4*)sH)[i] = __ldcg(hsrc + i);
        __syncthreads();

        float acc[4][5];
#pragma unroll
        for (int q = 0; q < 4; q++)
#pragma unroll
            for (int r = 0; r < 5; r++) acc[q][r] = 0.f;

        const float* hp = sH + (tb * 4) * H_ + td;
        const float* wp = sWs + (tr * 5) * WSTR + td;
#pragma unroll 4
        for (int k = 0; k < 64; k++) {
            const int d = k << 3;
            float hv[4], wv[5];
#pragma unroll
            for (int q = 0; q < 4; q++) hv[q] = hp[q * H_ + d];
#pragma unroll
            for (int r = 0; r < 5; r++) wv[r] = wp[r * WSTR + d];
#pragma unroll
            for (int q = 0; q < 4; q++)
#pragma unroll
                for (int r = 0; r < 5; r++) acc[q][r] += hv[q] * wv[r];
        }

#pragma unroll
        for (int q = 0; q < 4; q++)
#pragma unroll
            for (int r = 0; r < 5; r++) {
                float v = acc[q][r];
                v += __shfl_xor_sync(0xffffffffu, v, 1);
                v += __shfl_xor_sync(0xffffffffu, v, 2);
                v += __shfl_xor_sync(0xffffffffu, v, 4);
                if (td == 0) sRed[(tb * 4 + q) * NROW + tr * 5 + r] = v;
            }
        __syncthreads();

        if (tid < 128) {
            const int jj = tid & 3;
            const float* rb = sRed + bg * NROW + jj;
            float ps0 = rb[0]  + bsv[0];
            float ps1 = rb[4]  + bsv[1];
            float ps2 = rb[8]  + bsv[2];
            float ps3 = rb[12] + bsv[3];
            float ps4 = rb[16] + bsv[4];
            float iv = sigm(piv[0] + ps0);
            float fv = sigm(piv[1] + ps1);
            float gv = tanh_(piv[2] + ps2);
            float ov = sigm(piv[3] + ps3);
            float cn = iv * gv + fv * c_reg;
            float o1 = ov * tanh_(cn);
            float rv = sigm(piv[4] + ps4);
            float o2 = rv * o1 + (1.f - rv) * piv[5];
            bool  m  = (t < len);
            float hprev = sH[bg * H_ + j0];
            float hn = m ? o2 : hprev;
            c_reg    = m ? cn : c_reg;
            __stcg(&g_h[((t + 1) & 1) * BH + bg * H_ + j0], hn);
            out[((size_t)bg * T_ + t) * H_ + j0] = m ? o2 : 0.f;
            if (t == T_ - 1) {
                out[(size_t)B_ * T_ * H_ + bg * H_ + j0]      = hn;
                out[(size_t)B_ * T_ * H_ + BH + bg * H_ + j0] = c_reg;
            }
        }

        __threadfence();
        __syncthreads();
        epoch++;
        if (tid == 0) {
            atomicAdd(&g_bar, 1u);
            while (*(volatile unsigned*)&g_bar < NBLK * epoch) {}
        }
        __syncthreads();
    }
}

// ---------------------------------------------------------------------------
extern "C" void kernel_launch(void* const* d_in, const int* in_sizes, int n_in,
                              void* d_out, int out_size) {
    const float* x       = (const float*)d_in[0];
    const int*   lengths = (const int*)  d_in[1];
    const float* Wi      = (const float*)d_in[2];
    const float* bi      = (const float*)d_in[3];
    const float* Ws      = (const float*)d_in[4];
    const float* bs      = (const float*)d_in[5];
    float* out = (float*)d_out;

    const int smem = (NROW * WSTR + BH + B_ * NROW) * (int)sizeof(float);
    cudaFuncSetAttribute(lstm_scan_k, cudaFuncAttributeMaxDynamicSharedMemorySize, smem);

    init_k<<<1, 1>>>();

    __nv_bfloat16 *xhi, *xlo, *whi, *wlo;
    cudaGetSymbolAddress((void**)&xhi, g_xhi);
    cudaGetSymbolAddress((void**)&xlo, g_xlo);
    cudaGetSymbolAddress((void**)&whi, g_whi);
    cudaGetSymbolAddress((void**)&wlo, g_wlo);

    int nx4 = (B_ * T_ * D_) / 4;
    int nw4 = (SIXH * D_) / 4;
    split_k<<<(nx4 + 255) / 256, 256>>>(x, xhi, xlo, nx4);
    split_k<<<(nw4 + 255) / 256, 256>>>(Wi, whi, wlo, nw4);

    gemm_pi_mma_k<<<dim3(SIXH / 128, (B_ * T_) / 128), 256>>>(bi);
    lstm_scan_k<<<NBLK, NTHR, smem>>>(Ws, bs, lengths, out);
}

// round 3
// speedup vs baseline: 1.5171x; 1.2769x over previous
#include <cuda_runtime.h>
#include <cuda_bf16.h>
#include <cstdint>
#include <cstddef>

#define B_   32
#define T_   512
#define H_   512
#define D_   512
#define SIXH 3072
#define BH   (B_ * H_)

#define NBLK 128
#define JPB  4
#define NROW 20
#define NPAD 24          // padded Ws rows (3 n-tiles of 8)
#define SSTR 520         // bf16 row stride in smem (1040 B, ldmatrix conflict-free)
#define NTHR 256
#define NGRP 8           // barrier groups
#define GSZ  16          // blocks per group

// Scratch (device globals: allocation-free per harness rules)
__device__ float         g_pi[(size_t)B_ * T_ * SIXH];    // 201 MB
__device__ __nv_bfloat16 g_hhi[2 * BH];
__device__ __nv_bfloat16 g_hlo[2 * BH];
__device__ unsigned      g_bar_l1[NGRP];
__device__ unsigned      g_bar_l2;
__device__ __nv_bfloat16 g_xhi[(size_t)B_ * T_ * D_];
__device__ __nv_bfloat16 g_xlo[(size_t)B_ * T_ * D_];
__device__ __nv_bfloat16 g_whi[(size_t)SIXH * D_];
__device__ __nv_bfloat16 g_wlo[(size_t)SIXH * D_];

__global__ void init_k() {
    for (int i = 0; i < NGRP; i++) g_bar_l1[i] = 0u;
    g_bar_l2 = 0u;
}

// ---------------------------------------------------------------------------
// fp32 -> (bf16 hi, bf16 lo) split
// ---------------------------------------------------------------------------
__global__ void split_k(const float* __restrict__ src,
                        __nv_bfloat16* __restrict__ hi,
                        __nv_bfloat16* __restrict__ lo, int n4) {
    int i = blockIdx.x * blockDim.x + threadIdx.x;
    if (i >= n4) return;
    float4 f = ((const float4*)src)[i];
    __nv_bfloat16 h0 = __float2bfloat16(f.x);
    __nv_bfloat16 h1 = __float2bfloat16(f.y);
    __nv_bfloat16 h2 = __float2bfloat16(f.z);
    __nv_bfloat16 h3 = __float2bfloat16(f.w);
    __nv_bfloat162 hv0, hv1, lv0, lv1;
    hv0.x = h0; hv0.y = h1; hv1.x = h2; hv1.y = h3;
    lv0.x = __float2bfloat16(f.x - __bfloat162float(h0));
    lv0.y = __float2bfloat16(f.y - __bfloat162float(h1));
    lv1.x = __float2bfloat16(f.z - __bfloat162float(h2));
    lv1.y = __float2bfloat16(f.w - __bfloat162float(h3));
    ((__nv_bfloat162*)hi)[2 * i]     = hv0;
    ((__nv_bfloat162*)hi)[2 * i + 1] = hv1;
    ((__nv_bfloat162*)lo)[2 * i]     = lv0;
    ((__nv_bfloat162*)lo)[2 * i + 1] = lv1;
}

// ---------------------------------------------------------------------------
// MMA helpers
// ---------------------------------------------------------------------------
__device__ __forceinline__ void ldsm_x4(uint32_t& r0, uint32_t& r1,
                                        uint32_t& r2, uint32_t& r3, uint32_t a) {
    asm volatile("ldmatrix.sync.aligned.m8n8.x4.shared.b16 {%0,%1,%2,%3}, [%4];"
                 : "=r"(r0), "=r"(r1), "=r"(r2), "=r"(r3) : "r"(a));
}
__device__ __forceinline__ void ldsm_x2(uint32_t& r0, uint32_t& r1, uint32_t a) {
    asm volatile("ldmatrix.sync.aligned.m8n8.x2.shared.b16 {%0,%1}, [%2];"
                 : "=r"(r0), "=r"(r1) : "r"(a));
}
__device__ __forceinline__ void mma16816(float* c, const uint32_t* a,
                                         uint32_t b0, uint32_t b1) {
    asm volatile(
        "mma.sync.aligned.m16n8k16.row.col.f32.bf16.bf16.f32 "
        "{%0,%1,%2,%3},{%4,%5,%6,%7},{%8,%9},{%0,%1,%2,%3};"
        : "+f"(c[0]), "+f"(c[1]), "+f"(c[2]), "+f"(c[3])
        : "r"(a[0]), "r"(a[1]), "r"(a[2]), "r"(a[3]), "r"(b0), "r"(b1));
}

// ---------------------------------------------------------------------------
// Tensor-core input GEMM (unchanged from Round 2)
// ---------------------------------------------------------------------------
#define ASTR 48

__global__ __launch_bounds__(256) void gemm_pi_mma_k(const float* __restrict__ bi) {
    __shared__ char smem[4 * 128 * ASTR];
    char* sAhi = smem;
    char* sBhi = smem + 2 * 128 * ASTR;

    const int tid  = threadIdx.x;
    const int lane = tid & 31;
    const int warp = tid >> 5;
    const int wm   = warp >> 2;
    const int wn   = warp & 3;
    const int m0   = blockIdx.y * 128;
    const int n0   = blockIdx.x * 128;

    const int lrow  = tid >> 1;
    const int lhalf = tid & 1;
    const __nv_bfloat16* pxh = g_xhi + (size_t)(m0 + lrow) * D_ + lhalf * 8;
    const __nv_bfloat16* pxl = g_xlo + (size_t)(m0 + lrow) * D_ + lhalf * 8;
    const __nv_bfloat16* pwh = g_whi + (size_t)(n0 + lrow) * D_ + lhalf * 8;
    const __nv_bfloat16* pwl = g_wlo + (size_t)(n0 + lrow) * D_ + lhalf * 8;
    char* stA_hi = sAhi + lrow * ASTR + lhalf * 16;
    char* stB_hi = sBhi + lrow * ASTR + lhalf * 16;

    const int rowA = wm * 64 + (lane & 15);
    const uint32_t aAh = (uint32_t)__cvta_generic_to_shared(
        sAhi + rowA * ASTR + (lane >> 4) * 16);
    const uint32_t aAl = aAh + 128 * ASTR;
    const int rowB = wn * 32 + (lane & 7) + ((lane >> 4) << 3);
    const uint32_t aBh = (uint32_t)__cvta_generic_to_shared(
        sBhi + rowB * ASTR + ((lane >> 3) & 1) * 16);
    const uint32_t aBl = aBh + 128 * ASTR;

    float acc[4][4][4];
#pragma unroll
    for (int i = 0; i < 4; i++)
#pragma unroll
        for (int j = 0; j < 4; j++)
#pragma unroll
            for (int e = 0; e < 4; e++) acc[i][j][e] = 0.f;

    uint4 rxh = *(const uint4*)pxh;
    uint4 rxl = *(const uint4*)pxl;
    uint4 rwh = *(const uint4*)pwh;
    uint4 rwl = *(const uint4*)pwl;

    for (int kt = 0; kt < D_; kt += 16) {
        __syncthreads();
        *(uint4*)stA_hi               = rxh;
        *(uint4*)(stA_hi + 128*ASTR)  = rxl;
        *(uint4*)stB_hi               = rwh;
        *(uint4*)(stB_hi + 128*ASTR)  = rwl;
        __syncthreads();
        if (kt + 16 < D_) {
            rxh = *(const uint4*)(pxh + kt + 16);
            rxl = *(const uint4*)(pxl + kt + 16);
            rwh = *(const uint4*)(pwh + kt + 16);
            rwl = *(const uint4*)(pwl + kt + 16);
        }

        uint32_t ah[4][4], al[4][4], bh[4][2], bl[4][2];
#pragma unroll
        for (int mi = 0; mi < 4; mi++) {
            ldsm_x4(ah[mi][0], ah[mi][1], ah[mi][2], ah[mi][3], aAh + mi * 16 * ASTR);
            ldsm_x4(al[mi][0], al[mi][1], al[mi][2], al[mi][3], aAl + mi * 16 * ASTR);
        }
#pragma unroll
        for (int bg = 0; bg < 2; bg++) {
            ldsm_x4(bh[2 * bg][0], bh[2 * bg][1], bh[2 * bg + 1][0], bh[2 * bg + 1][1],
                    aBh + bg * 16 * ASTR);
            ldsm_x4(bl[2 * bg][0], bl[2 * bg][1], bl[2 * bg + 1][0], bl[2 * bg + 1][1],
                    aBl + bg * 16 * ASTR);
        }
#pragma unroll
        for (int mi = 0; mi < 4; mi++)
#pragma unroll
            for (int ni = 0; ni < 4; ni++) {
                mma16816(acc[mi][ni], ah[mi], bh[ni][0], bh[ni][1]);
                mma16816(acc[mi][ni], ah[mi], bl[ni][0], bl[ni][1]);
                mma16816(acc[mi][ni], al[mi], bh[ni][0], bh[ni][1]);
            }
    }

#pragma unroll
    for (int ni = 0; ni < 4; ni++) {
        const int n = n0 + wn * 32 + ni * 8 + 2 * (lane & 3);
        float b0 = bi[n], b1 = bi[n + 1];
#pragma unroll
        for (int mi = 0; mi < 4; mi++) {
            const int m = m0 + wm * 64 + mi * 16 + (lane >> 2);
            float* C0 = g_pi + (size_t)m * SIXH + n;
            float* C1 = g_pi + (size_t)(m + 8) * SIXH + n;
            *(float2*)C0 = make_float2(acc[mi][ni][0] + b0, acc[mi][ni][1] + b1);
            *(float2*)C1 = make_float2(acc[mi][ni][2] + b0, acc[mi][ni][3] + b1);
        }
    }
}

// ---------------------------------------------------------------------------
// Persistent recurrent scan — tensor-core dot phase.
// ---------------------------------------------------------------------------
__device__ __forceinline__ float sigm(float x)  { return 1.f / (1.f + __expf(-x)); }
__device__ __forceinline__ float tanh_(float x) { return 1.f - 2.f / (__expf(2.f * x) + 1.f); }

__global__ __launch_bounds__(NTHR, 1) void lstm_scan_k(
    const float* __restrict__ Ws, const float* __restrict__ bs,
    const int* __restrict__ lengths, float* __restrict__ out)
{
    extern __shared__ char smc[];
    __nv_bfloat16* sAh = (__nv_bfloat16*)smc;        // 32 x SSTR
    __nv_bfloat16* sAl = sAh + 32 * SSTR;            // 32 x SSTR
    __nv_bfloat16* sWh = sAl + 32 * SSTR;            // NPAD x SSTR
    __nv_bfloat16* sWl = sWh + NPAD * SSTR;          // NPAD x SSTR
    float*        sRed = (float*)(sWl + NPAD * SSTR);// 32 x NPAD

    const int tid  = threadIdx.x;
    const int blk  = blockIdx.x;
    const int lane = tid & 31;
    const int warp = tid >> 5;
    const int grp  = blk >> 4;                       // barrier group

    // --- Ws -> smem bf16 split (resident, rows >= NROW zero-padded) ---
    for (int i = tid; i < NPAD * (H_ / 8); i += NTHR) {
        int l  = i >> 6;                 // local row 0..23
        int d8 = (i & 63) << 3;
        __nv_bfloat16* ph = sWh + l * SSTR + d8;
        __nv_bfloat16* pl = sWl + l * SSTR + d8;
        if (l < NROW) {
            int row = (l >> 2) * H_ + blk * JPB + (l & 3);
            const float* p = Ws + (size_t)row * H_ + d8;
#pragma unroll
            for (int q = 0; q < 8; q++) {
                float f = p[q];
                __nv_bfloat16 hh = __float2bfloat16(f);
                ph[q] = hh;
                pl[q] = __float2bfloat16(f - __bfloat162float(hh));
            }
        } else {
#pragma unroll
            for (int q = 0; q < 8; q++) { ph[q] = __float2bfloat16(0.f); pl[q] = __float2bfloat16(0.f); }
        }
    }

    // MMA warp addressing (warps 0..5: mi in {0,1}, ni in {0,1,2})
    const int mi = warp / 3;
    const int ni = warp - mi * 3;
    const uint32_t aAh = (uint32_t)__cvta_generic_to_shared(
        sAh + (size_t)(mi * 16 + (lane & 15)) * SSTR) + (lane >> 4) * 16;
    const uint32_t aAl = aAh + 32 * SSTR * 2;
    const uint32_t aBh = (uint32_t)__cvta_generic_to_shared(
        sWh + (size_t)(ni * 8 + (lane & 7)) * SSTR) + ((lane >> 3) & 1) * 16;
    const uint32_t aBl = aBh + NPAD * SSTR * 2;

    // Gate threads: tid<128 owns (b = tid>>2, jj = tid&3); h & c in registers.
    float c_reg = 0.f, h_reg = 0.f;
    float bsv[5] = {0.f, 0.f, 0.f, 0.f, 0.f};
    int bg = 0, j0 = 0, len = 0;
    if (tid < 128) {
        bg = tid >> 2;
        j0 = blk * JPB + (tid & 3);
        len = lengths[bg];
#pragma unroll
        for (int g = 0; g < 5; g++) bsv[g] = bs[g * H_ + j0];
        __stcg((unsigned short*)&g_hhi[bg * H_ + j0], (unsigned short)0);
        __stcg((unsigned short*)&g_hlo[bg * H_ + j0], (unsigned short)0);
    }
    __threadfence();
    __syncthreads();
    unsigned epoch = 1;
    if (tid == 0) {
        unsigned old = atomicAdd(&g_bar_l1[grp], 1u);
        if (old == epoch * GSZ - 1) atomicAdd(&g_bar_l2, 1u);
        while (*(volatile unsigned*)&g_bar_l2 < epoch * NGRP) {}
    }
    __syncthreads();

    for (int t = 0; t < T_; t++) {
        // pi prefetch
        float piv[6] = {0.f, 0.f, 0.f, 0.f, 0.f, 0.f};
        if (tid < 128) {
            const float* pp = g_pi + ((size_t)bg * T_ + t) * SIXH + j0;
#pragma unroll
            for (int g = 0; g < 6; g++) piv[g] = __ldg(pp + g * H_);
        }

        // Load h hi/lo planes into padded smem (L2-coherent)
        {
            const uint4* ph = (const uint4*)(g_hhi + (t & 1) * BH);
            const uint4* pl = (const uint4*)(g_hlo + (t & 1) * BH);
            for (int i = tid; i < BH / 8; i += NTHR) {
                int r = i >> 6;
                int c = (i & 63) << 3;
                uint4 vh = __ldcg(ph + i);
                uint4 vl = __ldcg(pl + i);
                *(uint4*)(sAh + r * SSTR + c) = vh;
                *(uint4*)(sAl + r * SSTR + c) = vl;
            }
        }
        __syncthreads();

        // Tensor-core dot phase: ps[32 x 24] = h @ WsT (3-term bf16 split)
        if (warp < 6) {
            float acc[4] = {0.f, 0.f, 0.f, 0.f};
#pragma unroll 8
            for (int k = 0; k < 32; k++) {
                const uint32_t ko = k * 32;
                uint32_t ah[4], al[4], b0h, b1h, b0l, b1l;
                ldsm_x4(ah[0], ah[1], ah[2], ah[3], aAh + ko);
                ldsm_x4(al[0], al[1], al[2], al[3], aAl + ko);
                ldsm_x2(b0h, b1h, aBh + ko);
                ldsm_x2(b0l, b1l, aBl + ko);
                mma16816(acc, ah, b0h, b1h);
                mma16816(acc, al, b0h, b1h);
                mma16816(acc, ah, b0l, b1l);
            }
            const int br = mi * 16 + (lane >> 2);
            const int n  = ni * 8 + 2 * (lane & 3);
            *(float2*)&sRed[br * NPAD + n]       = make_float2(acc[0], acc[1]);
            *(float2*)&sRed[(br + 8) * NPAD + n] = make_float2(acc[2], acc[3]);
        }
        __syncthreads();

        // Gate phase
        if (tid < 128) {
            const int jj = tid & 3;
            const float* rb = sRed + bg * NPAD + jj;
            float ps0 = rb[0]  + bsv[0];
            float ps1 = rb[4]  + bsv[1];
            float ps2 = rb[8]  + bsv[2];
            float ps3 = rb[12] + bsv[3];
            float ps4 = rb[16] + bsv[4];
            float iv = sigm(piv[0] + ps0);
            float fv = sigm(piv[1] + ps1);
            float gv = tanh_(piv[2] + ps2);
            float ov = sigm(piv[3] + ps3);
            float cn = iv * gv + fv * c_reg;
            float o1 = ov * tanh_(cn);
            float rv = sigm(piv[4] + ps4);
            float o2 = rv * o1 + (1.f - rv) * piv[5];
            bool  m  = (t < len);
            h_reg = m ? o2 : h_reg;
            c_reg = m ? cn : c_reg;
            __nv_bfloat16 hh = __float2bfloat16(h_reg);
            __nv_bfloat16 hl = __float2bfloat16(h_reg - __bfloat162float(hh));
            const int idx = ((t + 1) & 1) * BH + bg * H_ + j0;
            __stcg((unsigned short*)&g_hhi[idx], __bfloat16_as_ushort(hh));
            __stcg((unsigned short*)&g_hlo[idx], __bfloat16_as_ushort(hl));
            out[((size_t)bg * T_ + t) * H_ + j0] = m ? o2 : 0.f;
            if (t == T_ - 1) {
                out[(size_t)B_ * T_ * H_ + bg * H_ + j0]      = h_reg;
                out[(size_t)B_ * T_ * H_ + BH + bg * H_ + j0] = c_reg;
            }
        }

        // Two-level grid barrier
        __threadfence();
        __syncthreads();
        epoch++;
        if (tid == 0) {
            unsigned old = atomicAdd(&g_bar_l1[grp], 1u);
            if (old == epoch * GSZ - 1) atomicAdd(&g_bar_l2, 1u);
            while (*(volatile unsigned*)&g_bar_l2 < epoch * NGRP) {}
        }
        __syncthreads();
    }
}

// ---------------------------------------------------------------------------
extern "C" void kernel_launch(void* const* d_in, const int* in_sizes, int n_in,
                              void* d_out, int out_size) {
    const float* x       = (const float*)d_in[0];
    const int*   lengths = (const int*)  d_in[1];
    const float* Wi      = (const float*)d_in[2];
    const float* bi      = (const float*)d_in[3];
    const float* Ws      = (const float*)d_in[4];
    const float* bs      = (const float*)d_in[5];
    float* out = (float*)d_out;

    const int smem = (32 + 32 + NPAD + NPAD) * SSTR * 2 + 32 * NPAD * 4; // 119,552 B
    cudaFuncSetAttribute(lstm_scan_k, cudaFuncAttributeMaxDynamicSharedMemorySize, smem);

    init_k<<<1, 1>>>();

    __nv_bfloat16 *xhi, *xlo, *whi, *wlo;
    cudaGetSymbolAddress((void**)&xhi, g_xhi);
    cudaGetSymbolAddress((void**)&xlo, g_xlo);
    cudaGetSymbolAddress((void**)&whi, g_whi);
    cudaGetSymbolAddress((void**)&wlo, g_wlo);

    int nx4 = (B_ * T_ * D_) / 4;
    int nw4 = (SIXH * D_) / 4;
    split_k<<<(nx4 + 255) / 256, 256>>>(x, xhi, xlo, nx4);
    split_k<<<(nw4 + 255) / 256, 256>>>(Wi, whi, wlo, nw4);

    gemm_pi_mma_k<<<dim3(SIXH / 128, (B_ * T_) / 128), 256>>>(bi);
    lstm_scan_k<<<NBLK, NTHR, smem>>>(Ws, bs, lengths, out);
}

// round 4
// speedup vs baseline: 1.6925x; 1.1156x over previous
#include <cuda_runtime.h>
#include <cuda_bf16.h>
#include <cstdint>
#include <cstddef>

#define B_   32
#define T_   512
#define H_   512
#define D_   512
#define SIXH 3072
#define BH   (B_ * H_)

#define NBLK 128
#define CPB  8           // h-columns per block
#define BGRP 16          // batch rows per group
#define NROW 40          // 5 gates * CPB
#define NPAD 48          // padded to 6 n-tiles
#define SSTR 520         // bf16 row stride in smem
#define NTHR 256

// Scratch (device globals: allocation-free per harness rules)
__device__ float         g_pi[(size_t)B_ * T_ * SIXH];
__device__ __nv_bfloat16 g_hhi[2 * BH];
__device__ __nv_bfloat16 g_hlo[2 * BH];
__device__ unsigned      g_bar_l1[2][8];
__device__ unsigned      g_bar_l2[2];
__device__ __nv_bfloat16 g_xhi[(size_t)B_ * T_ * D_];
__device__ __nv_bfloat16 g_xlo[(size_t)B_ * T_ * D_];
__device__ __nv_bfloat16 g_whi[(size_t)SIXH * D_];
__device__ __nv_bfloat16 g_wlo[(size_t)SIXH * D_];

__global__ void init_k() {
    for (int g = 0; g < 2; g++) {
        for (int i = 0; i < 8; i++) g_bar_l1[g][i] = 0u;
        g_bar_l2[g] = 0u;
    }
}

// ---------------------------------------------------------------------------
__global__ void split_k(const float* __restrict__ src,
                        __nv_bfloat16* __restrict__ hi,
                        __nv_bfloat16* __restrict__ lo, int n4) {
    int i = blockIdx.x * blockDim.x + threadIdx.x;
    if (i >= n4) return;
    float4 f = ((const float4*)src)[i];
    __nv_bfloat16 h0 = __float2bfloat16(f.x);
    __nv_bfloat16 h1 = __float2bfloat16(f.y);
    __nv_bfloat16 h2 = __float2bfloat16(f.z);
    __nv_bfloat16 h3 = __float2bfloat16(f.w);
    __nv_bfloat162 hv0, hv1, lv0, lv1;
    hv0.x = h0; hv0.y = h1; hv1.x = h2; hv1.y = h3;
    lv0.x = __float2bfloat16(f.x - __bfloat162float(h0));
    lv0.y = __float2bfloat16(f.y - __bfloat162float(h1));
    lv1.x = __float2bfloat16(f.z - __bfloat162float(h2));
    lv1.y = __float2bfloat16(f.w - __bfloat162float(h3));
    ((__nv_bfloat162*)hi)[2 * i]     = hv0;
    ((__nv_bfloat162*)hi)[2 * i + 1] = hv1;
    ((__nv_bfloat162*)lo)[2 * i]     = lv0;
    ((__nv_bfloat162*)lo)[2 * i + 1] = lv1;
}

// ---------------------------------------------------------------------------
__device__ __forceinline__ void ldsm_x4(uint32_t& r0, uint32_t& r1,
                                        uint32_t& r2, uint32_t& r3, uint32_t a) {
    asm volatile("ldmatrix.sync.aligned.m8n8.x4.shared.b16 {%0,%1,%2,%3}, [%4];"
                 : "=r"(r0), "=r"(r1), "=r"(r2), "=r"(r3) : "r"(a));
}
__device__ __forceinline__ void ldsm_x2(uint32_t& r0, uint32_t& r1, uint32_t a) {
    asm volatile("ldmatrix.sync.aligned.m8n8.x2.shared.b16 {%0,%1}, [%2];"
                 : "=r"(r0), "=r"(r1) : "r"(a));
}
__device__ __forceinline__ void mma16816(float* c, const uint32_t* a,
                                         uint32_t b0, uint32_t b1) {
    asm volatile(
        "mma.sync.aligned.m16n8k16.row.col.f32.bf16.bf16.f32 "
        "{%0,%1,%2,%3},{%4,%5,%6,%7},{%8,%9},{%0,%1,%2,%3};"
        : "+f"(c[0]), "+f"(c[1]), "+f"(c[2]), "+f"(c[3])
        : "r"(a[0]), "r"(a[1]), "r"(a[2]), "r"(a[3]), "r"(b0), "r"(b1));
}
__device__ __forceinline__ void cpa16(uint32_t dst, const void* src) {
    asm volatile("cp.async.cg.shared.global [%0], [%1], 16;"
                 :: "r"(dst), "l"(src));
}
__device__ __forceinline__ void cpa_commit() {
    asm volatile("cp.async.commit_group;");
}

// ---------------------------------------------------------------------------
// Tensor-core input GEMM, 3-stage cp.async pipeline.
// ---------------------------------------------------------------------------
#define ASTR  48
#define STAGE (4 * 128 * ASTR)   // 24576 B per stage

__global__ __launch_bounds__(256) void gemm_pi_mma_k(const float* __restrict__ bi) {
    extern __shared__ char smg[];

    const int tid  = threadIdx.x;
    const int lane = tid & 31;
    const int warp = tid >> 5;
    const int wm   = warp >> 2;
    const int wn   = warp & 3;
    const int m0   = blockIdx.y * 128;
    const int n0   = blockIdx.x * 128;

    const int lrow  = tid >> 1;
    const int lhalf = tid & 1;
    const __nv_bfloat16* pxh = g_xhi + (size_t)(m0 + lrow) * D_ + lhalf * 8;
    const __nv_bfloat16* pxl = g_xlo + (size_t)(m0 + lrow) * D_ + lhalf * 8;
    const __nv_bfloat16* pwh = g_whi + (size_t)(n0 + lrow) * D_ + lhalf * 8;
    const __nv_bfloat16* pwl = g_wlo + (size_t)(n0 + lrow) * D_ + lhalf * 8;

    const uint32_t sbase = (uint32_t)__cvta_generic_to_shared(smg);
    const uint32_t stoff = lrow * ASTR + lhalf * 16;

    // ldmatrix source addresses (stage-0 base)
    const int rowA = wm * 64 + (lane & 15);
    const uint32_t aAh0 = sbase + rowA * ASTR + (lane >> 4) * 16;
    const uint32_t aAl0 = aAh0 + 128 * ASTR;
    const int rowB = wn * 32 + (lane & 7) + ((lane >> 4) << 3);
    const uint32_t aBh0 = sbase + 2 * 128 * ASTR + rowB * ASTR + ((lane >> 3) & 1) * 16;
    const uint32_t aBl0 = aBh0 + 128 * ASTR;

    float acc[4][4][4];
#pragma unroll
    for (int i = 0; i < 4; i++)
#pragma unroll
        for (int j = 0; j < 4; j++)
#pragma unroll
            for (int e = 0; e < 4; e++) acc[i][j][e] = 0.f;

    auto commit_stage = [&](int p, int kts) {
        uint32_t d = sbase + p * STAGE + stoff;
        const int ko = kts * 16;
        cpa16(d,                  pxh + ko);
        cpa16(d + 128 * ASTR,     pxl + ko);
        cpa16(d + 2 * 128 * ASTR, pwh + ko);
        cpa16(d + 3 * 128 * ASTR, pwl + ko);
        cpa_commit();
    };

    commit_stage(0, 0);
    commit_stage(1, 1);

    for (int kts = 0; kts < 32; kts++) {
        if (kts + 2 < 32) {
            asm volatile("cp.async.wait_group 1;");
            __syncthreads();
            commit_stage((kts + 2) % 3, kts + 2);
        } else {
            asm volatile("cp.async.wait_group 0;");
            __syncthreads();
        }
        const uint32_t po = (kts % 3) * STAGE;

        uint32_t ah[4][4], al[4][4], bh[4][2], bl[4][2];
#pragma unroll
        for (int mi = 0; mi < 4; mi++) {
            ldsm_x4(ah[mi][0], ah[mi][1], ah[mi][2], ah[mi][3], aAh0 + po + mi * 16 * ASTR);
            ldsm_x4(al[mi][0], al[mi][1], al[mi][2], al[mi][3], aAl0 + po + mi * 16 * ASTR);
        }
#pragma unroll
        for (int bg = 0; bg < 2; bg++) {
            ldsm_x4(bh[2 * bg][0], bh[2 * bg][1], bh[2 * bg + 1][0], bh[2 * bg + 1][1],
                    aBh0 + po + bg * 16 * ASTR);
            ldsm_x4(bl[2 * bg][0], bl[2 * bg][1], bl[2 * bg + 1][0], bl[2 * bg + 1][1],
                    aBl0 + po + bg * 16 * ASTR);
        }
#pragma unroll
        for (int mi = 0; mi < 4; mi++)
#pragma unroll
            for (int ni = 0; ni < 4; ni++) {
                mma16816(acc[mi][ni], ah[mi], bh[ni][0], bh[ni][1]);
                mma16816(acc[mi][ni], ah[mi], bl[ni][0], bl[ni][1]);
                mma16816(acc[mi][ni], al[mi], bh[ni][0], bh[ni][1]);
            }
        __syncthreads();
    }

#pragma unroll
    for (int ni = 0; ni < 4; ni++) {
        const int n = n0 + wn * 32 + ni * 8 + 2 * (lane & 3);
        float b0 = bi[n], b1 = bi[n + 1];
#pragma unroll
        for (int mi = 0; mi < 4; mi++) {
            const int m = m0 + wm * 64 + mi * 16 + (lane >> 2);
            float* C0 = g_pi + (size_t)m * SIXH + n;
            float* C1 = g_pi + (size_t)(m + 8) * SIXH + n;
            *(float2*)C0 = make_float2(acc[mi][ni][0] + b0, acc[mi][ni][1] + b1);
            *(float2*)C1 = make_float2(acc[mi][ni][2] + b0, acc[mi][ni][3] + b1);
        }
    }
}

// ---------------------------------------------------------------------------
// Persistent recurrent scan: 2 batch-groups x 64 column-blocks.
// Block (group, cb): batch rows [group*16, group*16+16), cols cb*8..cb*8+7.
// ---------------------------------------------------------------------------
__device__ __forceinline__ float sigm(float x)  { return 1.f / (1.f + __expf(-x)); }
__device__ __forceinline__ float tanh_(float x) { return 1.f - 2.f / (__expf(2.f * x) + 1.f); }

__global__ __launch_bounds__(NTHR, 1) void lstm_scan_k(
    const float* __restrict__ Ws, const float* __restrict__ bs,
    const int* __restrict__ lengths, float* __restrict__ out)
{
    extern __shared__ char smc[];
    __nv_bfloat16* sAh = (__nv_bfloat16*)smc;          // 16 x SSTR
    __nv_bfloat16* sAl = sAh + 16 * SSTR;              // 16 x SSTR
    __nv_bfloat16* sWh = sAl + 16 * SSTR;              // NPAD x SSTR
    __nv_bfloat16* sWl = sWh + NPAD * SSTR;            // NPAD x SSTR
    float*        sRed = (float*)(sWl + NPAD * SSTR);  // 16 x NPAD

    const int tid   = threadIdx.x;
    const int blk   = blockIdx.x;
    const int lane  = tid & 31;
    const int warp  = tid >> 5;
    const int group = blk >> 6;        // 0..1
    const int cb    = blk & 63;        // column block
    const int sub   = cb >> 3;         // barrier subgroup 0..7

    // --- Ws -> smem bf16 split (rows >= NROW zero) ---
    for (int i = tid; i < NPAD * (H_ / 8); i += NTHR) {
        int l  = i >> 6;
        int d8 = (i & 63) << 3;
        __nv_bfloat16* ph = sWh + l * SSTR + d8;
        __nv_bfloat16* pl = sWl + l * SSTR + d8;
        if (l < NROW) {
            int row = (l >> 3) * H_ + cb * CPB + (l & 7);
            const float* p = Ws + (size_t)row * H_ + d8;
#pragma unroll
            for (int q = 0; q < 8; q++) {
                float f = p[q];
                __nv_bfloat16 hh = __float2bfloat16(f);
                ph[q] = hh;
                pl[q] = __float2bfloat16(f - __bfloat162float(hh));
            }
        } else {
#pragma unroll
            for (int q = 0; q < 8; q++) { ph[q] = __float2bfloat16(0.f); pl[q] = __float2bfloat16(0.f); }
        }
    }

    // MMA warp addressing: warps 0..5, ni = warp. A: 16x512, B: rows ni*8..+8.
    const int ni = warp;
    const uint32_t aAh = (uint32_t)__cvta_generic_to_shared(
        sAh + (size_t)(lane & 15) * SSTR) + (lane >> 4) * 16;
    const uint32_t aAl = aAh + 16 * SSTR * 2;
    const uint32_t aBh = (uint32_t)__cvta_generic_to_shared(
        sWh + (size_t)(ni * 8 + (lane & 7)) * SSTR) + ((lane >> 3) & 1) * 16;
    const uint32_t aBl = aBh + NPAD * SSTR * 2;

    // Gate threads: tid<128 owns (b_local = tid>>3, jj = tid&7).
    float c_reg = 0.f, h_reg = 0.f;
    float bsv[5] = {0.f, 0.f, 0.f, 0.f, 0.f};
    int bg = 0, j0 = 0, len = 0, b_local = 0;
    if (tid < 128) {
        b_local = tid >> 3;
        bg = group * BGRP + b_local;
        j0 = cb * CPB + (tid & 7);
        len = lengths[bg];
#pragma unroll
        for (int g = 0; g < 5; g++) bsv[g] = bs[g * H_ + j0];
        __stcg((unsigned short*)&g_hhi[bg * H_ + j0], (unsigned short)0);
        __stcg((unsigned short*)&g_hlo[bg * H_ + j0], (unsigned short)0);
    }
    __threadfence();
    __syncthreads();
    unsigned epoch = 1;
    if (tid == 0) {
        unsigned old = atomicAdd(&g_bar_l1[group][sub], 1u);
        if (old == epoch * 8 - 1) atomicAdd(&g_bar_l2[group], 1u);
        while (*(volatile unsigned*)&g_bar_l2[group] < epoch * 8) {}
    }
    __syncthreads();

    const int hbase = group * BGRP * H_;   // this group's 16-row slab

    for (int t = 0; t < T_; t++) {
        // pi prefetch
        float piv[6] = {0.f, 0.f, 0.f, 0.f, 0.f, 0.f};
        if (tid < 128) {
            const float* pp = g_pi + ((size_t)bg * T_ + t) * SIXH + j0;
#pragma unroll
            for (int g = 0; g < 6; g++) piv[g] = __ldg(pp + g * H_);
        }

        // h slab (16x512 hi+lo) -> smem via cp.async (L2-coherent)
        {
            const char* ph = (const char*)(g_hhi + (t & 1) * BH + hbase);
            const char* pl = (const char*)(g_hlo + (t & 1) * BH + hbase);
            const uint32_t dh = (uint32_t)__cvta_generic_to_shared(sAh);
            const uint32_t dl = (uint32_t)__cvta_generic_to_shared(sAl);
            for (int i = tid; i < BGRP * H_ / 8; i += NTHR) {   // 1024 iters/plane
                int r = i >> 6;
                int c = (i & 63) << 3;
                cpa16(dh + (r * SSTR + c) * 2, ph + i * 16);
                cpa16(dl + (r * SSTR + c) * 2, pl + i * 16);
            }
            cpa_commit();
            asm volatile("cp.async.wait_group 0;");
        }
        __syncthreads();

        // Tensor-core dot: ps[16 x 48] = h @ WsT (3-term bf16 split)
        if (warp < 6) {
            float acc[4] = {0.f, 0.f, 0.f, 0.f};
#pragma unroll 8
            for (int k = 0; k < 32; k++) {
                const uint32_t ko = k * 32;
                uint32_t ah[4], al[4], b0h, b1h, b0l, b1l;
                ldsm_x4(ah[0], ah[1], ah[2], ah[3], aAh + ko);
                ldsm_x4(al[0], al[1], al[2], al[3], aAl + ko);
                ldsm_x2(b0h, b1h, aBh + ko);
                ldsm_x2(b0l, b1l, aBl + ko);
                mma16816(acc, ah, b0h, b1h);
                mma16816(acc, al, b0h, b1h);
                mma16816(acc, ah, b0l, b1l);
            }
            const int br = lane >> 2;
            const int n  = ni * 8 + 2 * (lane & 3);
            *(float2*)&sRed[br * NPAD + n]       = make_float2(acc[0], acc[1]);
            *(float2*)&sRed[(br + 8) * NPAD + n] = make_float2(acc[2], acc[3]);
        }
        __syncthreads();

        // Gate phase
        if (tid < 128) {
            const int jj = tid & 7;
            const float* rb = sRed + b_local * NPAD + jj;
            float ps0 = rb[0]  + bsv[0];
            float ps1 = rb[8]  + bsv[1];
            float ps2 = rb[16] + bsv[2];
            float ps3 = rb[24] + bsv[3];
            float ps4 = rb[32] + bsv[4];
            float iv = sigm(piv[0] + ps0);
            float fv = sigm(piv[1] + ps1);
            float gv = tanh_(piv[2] + ps2);
            float ov = sigm(piv[3] + ps3);
            float cn = iv * gv + fv * c_reg;
            float o1 = ov * tanh_(cn);
            float rv = sigm(piv[4] + ps4);
            float o2 = rv * o1 + (1.f - rv) * piv[5];
            bool  m  = (t < len);
            h_reg = m ? o2 : h_reg;
            c_reg = m ? cn : c_reg;
            __nv_bfloat16 hh = __float2bfloat16(h_reg);
            __nv_bfloat16 hl = __float2bfloat16(h_reg - __bfloat162float(hh));
            const int idx = ((t + 1) & 1) * BH + bg * H_ + j0;
            __stcg((unsigned short*)&g_hhi[idx], __bfloat16_as_ushort(hh));
            __stcg((unsigned short*)&g_hlo[idx], __bfloat16_as_ushort(hl));
            out[((size_t)bg * T_ + t) * H_ + j0] = m ? o2 : 0.f;
            if (t == T_ - 1) {
                out[(size_t)B_ * T_ * H_ + bg * H_ + j0]      = h_reg;
                out[(size_t)B_ * T_ * H_ + BH + bg * H_ + j0] = c_reg;
            }
        }

        // Per-group two-level barrier
        __threadfence();
        __syncthreads();
        epoch++;
        if (tid == 0) {
            unsigned old = atomicAdd(&g_bar_l1[group][sub], 1u);
            if (old == epoch * 8 - 1) atomicAdd(&g_bar_l2[group], 1u);
            while (*(volatile unsigned*)&g_bar_l2[group] < epoch * 8) {}
        }
        __syncthreads();
    }
}

// ---------------------------------------------------------------------------
extern "C" void kernel_launch(void* const* d_in, const int* in_sizes, int n_in,
                              void* d_out, int out_size) {
    const float* x       = (const float*)d_in[0];
    const int*   lengths = (const int*)  d_in[1];
    const float* Wi      = (const float*)d_in[2];
    const float* bi      = (const float*)d_in[3];
    const float* Ws      = (const float*)d_in[4];
    const float* bs      = (const float*)d_in[5];
    float* out = (float*)d_out;

    const int smem_scan = (16 + 16 + NPAD + NPAD) * SSTR * 2 + 16 * NPAD * 4; // 136,192 B
    const int smem_gemm = 3 * STAGE;                                          // 73,728 B
    cudaFuncSetAttribute(lstm_scan_k,  cudaFuncAttributeMaxDynamicSharedMemorySize, smem_scan);
    cudaFuncSetAttribute(gemm_pi_mma_k, cudaFuncAttributeMaxDynamicSharedMemorySize, smem_gemm);

    init_k<<<1, 1>>>();

    __nv_bfloat16 *xhi, *xlo, *whi, *wlo;
    cudaGetSymbolAddress((void**)&xhi, g_xhi);
    cudaGetSymbolAddress((void**)&xlo, g_xlo);
    cudaGetSymbolAddress((void**)&whi, g_whi);
    cudaGetSymbolAddress((void**)&wlo, g_wlo);

    int nx4 = (B_ * T_ * D_) / 4;
    int nw4 = (SIXH * D_) / 4;
    split_k<<<(nx4 + 255) / 256, 256>>>(x, xhi, xlo, nx4);
    split_k<<<(nw4 + 255) / 256, 256>>>(Wi, whi, wlo, nw4);

    gemm_pi_mma_k<<<dim3(SIXH / 128, (B_ * T_) / 128), 256, smem_gemm>>>(bi);
    lstm_scan_k<<<NBLK, NTHR, smem_scan>>>(Ws, bs, lengths, out);
}

// round 5
// speedup vs baseline: 1.7797x; 1.0516x over previous
#include <cuda_runtime.h>
#include <cuda_bf16.h>
#include <cstdint>
#include <cstddef>

#define B_   32
#define T_   512
#define H_   512
#define D_   512
#define SIXH 3072
#define BH   (B_ * H_)

#define NBLK 128
#define CPB  8           // h-columns per block
#define BGRP 16          // batch rows per group
#define NROW 40          // 5 gates * CPB (exactly 5 n-tiles of 8)
#define SSTR 520         // bf16 row stride in smem
#define PSTR 44          // partial row stride (floats), store-conflict-free
#define NTHR 256

// Scratch (device globals: allocation-free per harness rules)
__device__ float         g_pi[(size_t)B_ * T_ * SIXH];
__device__ __nv_bfloat16 g_hhi[2 * BH];
__device__ __nv_bfloat16 g_hlo[2 * BH];
__device__ unsigned      g_bar_l1[2][8];
__device__ unsigned      g_bar_l2[2];
__device__ __nv_bfloat16 g_xhi[(size_t)B_ * T_ * D_];
__device__ __nv_bfloat16 g_xlo[(size_t)B_ * T_ * D_];
__device__ __nv_bfloat16 g_whi[(size_t)SIXH * D_];
__device__ __nv_bfloat16 g_wlo[(size_t)SIXH * D_];

__global__ void init_k() {
    for (int g = 0; g < 2; g++) {
        for (int i = 0; i < 8; i++) g_bar_l1[g][i] = 0u;
        g_bar_l2[g] = 0u;
    }
}

// ---------------------------------------------------------------------------
__global__ void split_k(const float* __restrict__ src,
                        __nv_bfloat16* __restrict__ hi,
                        __nv_bfloat16* __restrict__ lo, int n4) {
    int i = blockIdx.x * blockDim.x + threadIdx.x;
    if (i >= n4) return;
    float4 f = ((const float4*)src)[i];
    __nv_bfloat16 h0 = __float2bfloat16(f.x);
    __nv_bfloat16 h1 = __float2bfloat16(f.y);
    __nv_bfloat16 h2 = __float2bfloat16(f.z);
    __nv_bfloat16 h3 = __float2bfloat16(f.w);
    __nv_bfloat162 hv0, hv1, lv0, lv1;
    hv0.x = h0; hv0.y = h1; hv1.x = h2; hv1.y = h3;
    lv0.x = __float2bfloat16(f.x - __bfloat162float(h0));
    lv0.y = __float2bfloat16(f.y - __bfloat162float(h1));
    lv1.x = __float2bfloat16(f.z - __bfloat162float(h2));
    lv1.y = __float2bfloat16(f.w - __bfloat162float(h3));
    ((__nv_bfloat162*)hi)[2 * i]     = hv0;
    ((__nv_bfloat162*)hi)[2 * i + 1] = hv1;
    ((__nv_bfloat162*)lo)[2 * i]     = lv0;
    ((__nv_bfloat162*)lo)[2 * i + 1] = lv1;
}

// ---------------------------------------------------------------------------
__device__ __forceinline__ void ldsm_x4(uint32_t& r0, uint32_t& r1,
                                        uint32_t& r2, uint32_t& r3, uint32_t a) {
    asm volatile("ldmatrix.sync.aligned.m8n8.x4.shared.b16 {%0,%1,%2,%3}, [%4];"
                 : "=r"(r0), "=r"(r1), "=r"(r2), "=r"(r3) : "r"(a));
}
__device__ __forceinline__ void ldsm_x2(uint32_t& r0, uint32_t& r1, uint32_t a) {
    asm volatile("ldmatrix.sync.aligned.m8n8.x2.shared.b16 {%0,%1}, [%2];"
                 : "=r"(r0), "=r"(r1) : "r"(a));
}
__device__ __forceinline__ void mma16816(float* c, const uint32_t* a,
                                         uint32_t b0, uint32_t b1) {
    asm volatile(
        "mma.sync.aligned.m16n8k16.row.col.f32.bf16.bf16.f32 "
        "{%0,%1,%2,%3},{%4,%5,%6,%7},{%8,%9},{%0,%1,%2,%3};"
        : "+f"(c[0]), "+f"(c[1]), "+f"(c[2]), "+f"(c[3])
        : "r"(a[0]), "r"(a[1]), "r"(a[2]), "r"(a[3]), "r"(b0), "r"(b1));
}
__device__ __forceinline__ void cpa16(uint32_t dst, const void* src) {
    asm volatile("cp.async.cg.shared.global [%0], [%1], 16;"
                 :: "r"(dst), "l"(src));
}
__device__ __forceinline__ void cpa_commit() {
    asm volatile("cp.async.commit_group;");
}

// ---------------------------------------------------------------------------
// Tensor-core input GEMM, 3-stage cp.async pipeline, ONE sync per k-tile.
// ---------------------------------------------------------------------------
#define ASTR  48
#define STAGE (4 * 128 * ASTR)   // 24576 B per stage

__global__ __launch_bounds__(256) void gemm_pi_mma_k(const float* __restrict__ bi) {
    extern __shared__ char smg[];

    const int tid  = threadIdx.x;
    const int lane = tid & 31;
    const int warp = tid >> 5;
    const int wm   = warp >> 2;
    const int wn   = warp & 3;
    const int m0   = blockIdx.y * 128;
    const int n0   = blockIdx.x * 128;

    const int lrow  = tid >> 1;
    const int lhalf = tid & 1;
    const __nv_bfloat16* pxh = g_xhi + (size_t)(m0 + lrow) * D_ + lhalf * 8;
    const __nv_bfloat16* pxl = g_xlo + (size_t)(m0 + lrow) * D_ + lhalf * 8;
    const __nv_bfloat16* pwh = g_whi + (size_t)(n0 + lrow) * D_ + lhalf * 8;
    const __nv_bfloat16* pwl = g_wlo + (size_t)(n0 + lrow) * D_ + lhalf * 8;

    const uint32_t sbase = (uint32_t)__cvta_generic_to_shared(smg);
    const uint32_t stoff = lrow * ASTR + lhalf * 16;

    const int rowA = wm * 64 + (lane & 15);
    const uint32_t aAh0 = sbase + rowA * ASTR + (lane >> 4) * 16;
    const uint32_t aAl0 = aAh0 + 128 * ASTR;
    const int rowB = wn * 32 + (lane & 7) + ((lane >> 4) << 3);
    const uint32_t aBh0 = sbase + 2 * 128 * ASTR + rowB * ASTR + ((lane >> 3) & 1) * 16;
    const uint32_t aBl0 = aBh0 + 128 * ASTR;

    float acc[4][4][4];
#pragma unroll
    for (int i = 0; i < 4; i++)
#pragma unroll
        for (int j = 0; j < 4; j++)
#pragma unroll
            for (int e = 0; e < 4; e++) acc[i][j][e] = 0.f;

    auto commit_stage = [&](int p, int kts) {
        uint32_t d = sbase + p * STAGE + stoff;
        const int ko = kts * 16;
        cpa16(d,                  pxh + ko);
        cpa16(d + 128 * ASTR,     pxl + ko);
        cpa16(d + 2 * 128 * ASTR, pwh + ko);
        cpa16(d + 3 * 128 * ASTR, pwl + ko);
        cpa_commit();
    };

    commit_stage(0, 0);
    commit_stage(1, 1);

    for (int kts = 0; kts < 32; kts++) {
        if (kts < 31) asm volatile("cp.async.wait_group 1;");
        else          asm volatile("cp.async.wait_group 0;");
        __syncthreads();
        if (kts + 2 < 32) commit_stage((kts + 2) % 3, kts + 2);

        const uint32_t po = (kts % 3) * STAGE;

        uint32_t ah[4][4], al[4][4], bh[4][2], bl[4][2];
#pragma unroll
        for (int mi = 0; mi < 4; mi++) {
            ldsm_x4(ah[mi][0], ah[mi][1], ah[mi][2], ah[mi][3], aAh0 + po + mi * 16 * ASTR);
            ldsm_x4(al[mi][0], al[mi][1], al[mi][2], al[mi][3], aAl0 + po + mi * 16 * ASTR);
        }
#pragma unroll
        for (int bg = 0; bg < 2; bg++) {
            ldsm_x4(bh[2 * bg][0], bh[2 * bg][1], bh[2 * bg + 1][0], bh[2 * bg + 1][1],
                    aBh0 + po + bg * 16 * ASTR);
            ldsm_x4(bl[2 * bg][0], bl[2 * bg][1], bl[2 * bg + 1][0], bl[2 * bg + 1][1],
                    aBl0 + po + bg * 16 * ASTR);
        }
#pragma unroll
        for (int mi = 0; mi < 4; mi++)
#pragma unroll
            for (int ni = 0; ni < 4; ni++) {
                mma16816(acc[mi][ni], ah[mi], bh[ni][0], bh[ni][1]);
                mma16816(acc[mi][ni], ah[mi], bl[ni][0], bl[ni][1]);
                mma16816(acc[mi][ni], al[mi], bh[ni][0], bh[ni][1]);
            }
    }

#pragma unroll
    for (int ni = 0; ni < 4; ni++) {
        const int n = n0 + wn * 32 + ni * 8 + 2 * (lane & 3);
        float b0 = bi[n], b1 = bi[n + 1];
#pragma unroll
        for (int mi = 0; mi < 4; mi++) {
            const int m = m0 + wm * 64 + mi * 16 + (lane >> 2);
            float* C0 = g_pi + (size_t)m * SIXH + n;
            float* C1 = g_pi + (size_t)(m + 8) * SIXH + n;
            *(float2*)C0 = make_float2(acc[mi][ni][0] + b0, acc[mi][ni][1] + b1);
            *(float2*)C1 = make_float2(acc[mi][ni][2] + b0, acc[mi][ni][3] + b1);
        }
    }
}

// ---------------------------------------------------------------------------
// Persistent recurrent scan: 2 groups x 64 col-blocks.
// MMA: 8-way k-split (each warp: 5 n-tiles over a 64-wide k-chunk).
// Gate threads reduce the 8 partials directly.
// ---------------------------------------------------------------------------
__device__ __forceinline__ float sigm(float x)  { return 1.f / (1.f + __expf(-x)); }
__device__ __forceinline__ float tanh_(float x) { return 1.f - 2.f / (__expf(2.f * x) + 1.f); }

__global__ __launch_bounds__(NTHR, 1) void lstm_scan_k(
    const float* __restrict__ Ws, const float* __restrict__ bs,
    const int* __restrict__ lengths, float* __restrict__ out)
{
    extern __shared__ char smc[];
    __nv_bfloat16* sAh  = (__nv_bfloat16*)smc;           // 16 x SSTR
    __nv_bfloat16* sAl  = sAh + 16 * SSTR;               // 16 x SSTR
    __nv_bfloat16* sWh  = sAl + 16 * SSTR;               // NROW x SSTR
    __nv_bfloat16* sWl  = sWh + NROW * SSTR;             // NROW x SSTR
    float*         sPart = (float*)(sWl + NROW * SSTR);  // 8 x 16 x PSTR

    const int tid   = threadIdx.x;
    const int blk   = blockIdx.x;
    const int lane  = tid & 31;
    const int warp  = tid >> 5;
    const int group = blk >> 6;
    const int cb    = blk & 63;
    const int sub   = cb >> 3;

    // --- Ws -> smem bf16 split (exactly NROW rows) ---
    for (int i = tid; i < NROW * (H_ / 8); i += NTHR) {
        int l  = i >> 6;
        int d8 = (i & 63) << 3;
        __nv_bfloat16* ph = sWh + l * SSTR + d8;
        __nv_bfloat16* pl = sWl + l * SSTR + d8;
        int row = (l >> 3) * H_ + cb * CPB + (l & 7);
        const float* p = Ws + (size_t)row * H_ + d8;
#pragma unroll
        for (int q = 0; q < 8; q++) {
            float f = p[q];
            __nv_bfloat16 hh = __float2bfloat16(f);
            ph[q] = hh;
            pl[q] = __float2bfloat16(f - __bfloat162float(hh));
        }
    }

    // MMA addressing: warp = k-chunk (kh), 64 k-elems each.
    const int kh = warp;
    const uint32_t aAh = (uint32_t)__cvta_generic_to_shared(
        sAh + (size_t)(lane & 15) * SSTR) + (lane >> 4) * 16 + kh * 128;
    const uint32_t aAl = aAh + 16 * SSTR * 2;
    const uint32_t aBh = (uint32_t)__cvta_generic_to_shared(
        sWh + (size_t)(lane & 7) * SSTR) + ((lane >> 3) & 1) * 16 + kh * 128;
    const uint32_t aBl = aBh + NROW * SSTR * 2;

    // Gate threads: tid<128 owns (b_local = tid>>3, jj = tid&7).
    float c_reg = 0.f, h_reg = 0.f;
    float bsv[5] = {0.f, 0.f, 0.f, 0.f, 0.f};
    int bg = 0, j0 = 0, len = 0, b_local = 0;
    if (tid < 128) {
        b_local = tid >> 3;
        bg = group * BGRP + b_local;
        j0 = cb * CPB + (tid & 7);
        len = lengths[bg];
#pragma unroll
        for (int g = 0; g < 5; g++) bsv[g] = bs[g * H_ + j0];
        __stcg((unsigned short*)&g_hhi[bg * H_ + j0], (unsigned short)0);
        __stcg((unsigned short*)&g_hlo[bg * H_ + j0], (unsigned short)0);
    }
    __threadfence();
    __syncthreads();
    unsigned epoch = 1;
    if (tid == 0) {
        unsigned old = atomicAdd(&g_bar_l1[group][sub], 1u);
        if (old == epoch * 8 - 1) atomicAdd(&g_bar_l2[group], 1u);
        while (*(volatile unsigned*)&g_bar_l2[group] < epoch * 8) {}
    }
    __syncthreads();

    const int hbase = group * BGRP * H_;

    // Deep pi prefetch: pv_cur holds step t, pv_nxt is loading step t+1.
    float pv_cur[6] = {0,0,0,0,0,0}, pv_nxt[6] = {0,0,0,0,0,0};
    const float* ppi = (tid < 128) ? g_pi + (size_t)bg * T_ * SIXH + j0 : g_pi;
    if (tid < 128) {
#pragma unroll
        for (int g = 0; g < 6; g++) pv_cur[g] = __ldg(ppi + g * H_);
    }

    for (int t = 0; t < T_; t++) {
        // issue next step's pi loads (full-step latency slack)
        if (tid < 128 && t + 1 < T_) {
            const float* pp = ppi + (size_t)(t + 1) * SIXH;
#pragma unroll
            for (int g = 0; g < 6; g++) pv_nxt[g] = __ldg(pp + g * H_);
        }

        // h slab (16x512 hi+lo) -> smem via cp.async (L2-coherent)
        {
            const char* ph = (const char*)(g_hhi + (t & 1) * BH + hbase);
            const char* pl = (const char*)(g_hlo + (t & 1) * BH + hbase);
            const uint32_t dh = (uint32_t)__cvta_generic_to_shared(sAh);
            const uint32_t dl = (uint32_t)__cvta_generic_to_shared(sAl);
            for (int i = tid; i < BGRP * H_ / 8; i += NTHR) {
                int r = i >> 6;
                int c = (i & 63) << 3;
                cpa16(dh + (r * SSTR + c) * 2, ph + i * 16);
                cpa16(dl + (r * SSTR + c) * 2, pl + i * 16);
            }
            cpa_commit();
            asm volatile("cp.async.wait_group 0;");
        }
        __syncthreads();

        // MMA: warp kh computes 16x40 partial over k-chunk [kh*64, kh*64+64)
        {
            float acc[5][4];
#pragma unroll
            for (int ni = 0; ni < 5; ni++)
#pragma unroll
                for (int e = 0; e < 4; e++) acc[ni][e] = 0.f;
#pragma unroll
            for (int kk = 0; kk < 4; kk++) {
                const uint32_t ko = kk * 32;
                uint32_t ah[4], al[4];
                ldsm_x4(ah[0], ah[1], ah[2], ah[3], aAh + ko);
                ldsm_x4(al[0], al[1], al[2], al[3], aAl + ko);
#pragma unroll
                for (int ni = 0; ni < 5; ni++) {
                    const uint32_t bo = ko + ni * 8 * SSTR * 2;
                    uint32_t b0h, b1h, b0l, b1l;
                    ldsm_x2(b0h, b1h, aBh + bo);
                    ldsm_x2(b0l, b1l, aBl + bo);
                    mma16816(acc[ni], ah, b0h, b1h);
                    mma16816(acc[ni], al, b0h, b1h);
                    mma16816(acc[ni], ah, b0l, b1l);
                }
            }
            // store partials
            float* pp = sPart + kh * 16 * PSTR;
            const int r = lane >> 2;
#pragma unroll
            for (int ni = 0; ni < 5; ni++) {
                const int n = ni * 8 + 2 * (lane & 3);
                *(float2*)&pp[r * PSTR + n]       = make_float2(acc[ni][0], acc[ni][1]);
                *(float2*)&pp[(r + 8) * PSTR + n] = make_float2(acc[ni][2], acc[ni][3]);
            }
        }
        __syncthreads();

        // Gate phase: reduce 8 partials + gates
        if (tid < 128) {
            const int jj = tid & 7;
            float ps[5];
#pragma unroll
            for (int g = 0; g < 5; g++) {
                float s = 0.f;
#pragma unroll
                for (int w = 0; w < 8; w++)
                    s += sPart[w * 16 * PSTR + b_local * PSTR + g * 8 + jj];
                ps[g] = s + bsv[g];
            }
            float iv = sigm(pv_cur[0] + ps[0]);
            float fv = sigm(pv_cur[1] + ps[1]);
            float gv = tanh_(pv_cur[2] + ps[2]);
            float ov = sigm(pv_cur[3] + ps[3]);
            float cn = iv * gv + fv * c_reg;
            float o1 = ov * tanh_(cn);
            float rv = sigm(pv_cur[4] + ps[4]);
            float o2 = rv * o1 + (1.f - rv) * pv_cur[5];
            bool  m  = (t < len);
            h_reg = m ? o2 : h_reg;
            c_reg = m ? cn : c_reg;
            __nv_bfloat16 hh = __float2bfloat16(h_reg);
            __nv_bfloat16 hl = __float2bfloat16(h_reg - __bfloat162float(hh));
            const int idx = ((t + 1) & 1) * BH + bg * H_ + j0;
            __stcg((unsigned short*)&g_hhi[idx], __bfloat16_as_ushort(hh));
            __stcg((unsigned short*)&g_hlo[idx], __bfloat16_as_ushort(hl));
            out[((size_t)bg * T_ + t) * H_ + j0] = m ? o2 : 0.f;
            if (t == T_ - 1) {
                out[(size_t)B_ * T_ * H_ + bg * H_ + j0]      = h_reg;
                out[(size_t)B_ * T_ * H_ + BH + bg * H_ + j0] = c_reg;
            }
        }
#pragma unroll
        for (int g = 0; g < 6; g++) pv_cur[g] = pv_nxt[g];

        // Per-group two-level barrier
        __threadfence();
        __syncthreads();
        epoch++;
        if (tid == 0) {
            unsigned old = atomicAdd(&g_bar_l1[group][sub], 1u);
            if (old == epoch * 8 - 1) atomicAdd(&g_bar_l2[group], 1u);
            while (*(volatile unsigned*)&g_bar_l2[group] < epoch * 8) {}
        }
        __syncthreads();
    }
}

// ---------------------------------------------------------------------------
extern "C" void kernel_launch(void* const* d_in, const int* in_sizes, int n_in,
                              void* d_out, int out_size) {
    const float* x       = (const float*)d_in[0];
    const int*   lengths = (const int*)  d_in[1];
    const float* Wi      = (const float*)d_in[2];
    const float* bi      = (const float*)d_in[3];
    const float* Ws      = (const float*)d_in[4];
    const float* bs      = (const float*)d_in[5];
    float* out = (float*)d_out;

    const int smem_scan = (16 + 16 + NROW + NROW) * SSTR * 2 + 8 * 16 * PSTR * 4; // 139,008 B
    const int smem_gemm = 3 * STAGE;
    cudaFuncSetAttribute(lstm_scan_k,   cudaFuncAttributeMaxDynamicSharedMemorySize, smem_scan);
    cudaFuncSetAttribute(gemm_pi_mma_k, cudaFuncAttributeMaxDynamicSharedMemorySize, smem_gemm);

    init_k<<<1, 1>>>();

    __nv_bfloat16 *xhi, *xlo, *whi, *wlo;
    cudaGetSymbolAddress((void**)&xhi, g_xhi);
    cudaGetSymbolAddress((void**)&xlo, g_xlo);
    cudaGetSymbolAddress((void**)&whi, g_whi);
    cudaGetSymbolAddress((void**)&wlo, g_wlo);

    int nx4 = (B_ * T_ * D_) / 4;
    int nw4 = (SIXH * D_) / 4;
    split_k<<<(nx4 + 255) / 256, 256>>>(x, xhi, xlo, nx4);
    split_k<<<(nw4 + 255) / 256, 256>>>(Wi, whi, wlo, nw4);

    gemm_pi_mma_k<<<dim3(SIXH / 128, (B_ * T_) / 128), 256, smem_gemm>>>(bi);
    lstm_scan_k<<<NBLK, NTHR, smem_scan>>>(Ws, bs, lengths, out);
}

// round 6
// speedup vs baseline: 2.1336x; 1.1988x over previous
#include <cuda_runtime.h>
#include <cuda_bf16.h>
#include <cstdint>
#include <cstddef>

#define B_   32
#define T_   512
#define H_   512
#define D_   512
#define SIXH 3072
#define BH   (B_ * H_)

#define NBLK 128
#define CPB  8           // h-columns per block
#define BGRP 16          // batch rows per group
#define NROW 40          // 5 gates * CPB (exactly 5 n-tiles of 8)
#define SSTR 520         // bf16 row stride in smem
#define PSTR 44          // partial row stride (floats)
#define NTHR 256

// Scratch (device globals: allocation-free per harness rules)
__device__ float         g_pi[(size_t)B_ * T_ * SIXH];
__device__ __nv_bfloat16 g_hhi[2 * BH];
__device__ __nv_bfloat16 g_hlo[2 * BH];
__device__ unsigned      g_cnt[2][8];    // per-group per-subgroup arrival counters
__device__ __nv_bfloat16 g_xhi[(size_t)B_ * T_ * D_];
__device__ __nv_bfloat16 g_xlo[(size_t)B_ * T_ * D_];
__device__ __nv_bfloat16 g_whi[(size_t)SIXH * D_];
__device__ __nv_bfloat16 g_wlo[(size_t)SIXH * D_];

__global__ void init_k() {
    for (int g = 0; g < 2; g++)
        for (int i = 0; i < 8; i++) g_cnt[g][i] = 0u;
}

// ---------------------------------------------------------------------------
__global__ void split_k(const float* __restrict__ src,
                        __nv_bfloat16* __restrict__ hi,
                        __nv_bfloat16* __restrict__ lo, int n4) {
    int i = blockIdx.x * blockDim.x + threadIdx.x;
    if (i >= n4) return;
    float4 f = ((const float4*)src)[i];
    __nv_bfloat16 h0 = __float2bfloat16(f.x);
    __nv_bfloat16 h1 = __float2bfloat16(f.y);
    __nv_bfloat16 h2 = __float2bfloat16(f.z);
    __nv_bfloat16 h3 = __float2bfloat16(f.w);
    __nv_bfloat162 hv0, hv1, lv0, lv1;
    hv0.x = h0; hv0.y = h1; hv1.x = h2; hv1.y = h3;
    lv0.x = __float2bfloat16(f.x - __bfloat162float(h0));
    lv0.y = __float2bfloat16(f.y - __bfloat162float(h1));
    lv1.x = __float2bfloat16(f.z - __bfloat162float(h2));
    lv1.y = __float2bfloat16(f.w - __bfloat162float(h3));
    ((__nv_bfloat162*)hi)[2 * i]     = hv0;
    ((__nv_bfloat162*)hi)[2 * i + 1] = hv1;
    ((__nv_bfloat162*)lo)[2 * i]     = lv0;
    ((__nv_bfloat162*)lo)[2 * i + 1] = lv1;
}

// ---------------------------------------------------------------------------
__device__ __forceinline__ void ldsm_x4(uint32_t& r0, uint32_t& r1,
                                        uint32_t& r2, uint32_t& r3, uint32_t a) {
    asm volatile("ldmatrix.sync.aligned.m8n8.x4.shared.b16 {%0,%1,%2,%3}, [%4];"
                 : "=r"(r0), "=r"(r1), "=r"(r2), "=r"(r3) : "r"(a));
}
__device__ __forceinline__ void ldsm_x2(uint32_t& r0, uint32_t& r1, uint32_t a) {
    asm volatile("ldmatrix.sync.aligned.m8n8.x2.shared.b16 {%0,%1}, [%2];"
                 : "=r"(r0), "=r"(r1) : "r"(a));
}
__device__ __forceinline__ void mma16816(float* c, const uint32_t* a,
                                         uint32_t b0, uint32_t b1) {
    asm volatile(
        "mma.sync.aligned.m16n8k16.row.col.f32.bf16.bf16.f32 "
        "{%0,%1,%2,%3},{%4,%5,%6,%7},{%8,%9},{%0,%1,%2,%3};"
        : "+f"(c[0]), "+f"(c[1]), "+f"(c[2]), "+f"(c[3])
        : "r"(a[0]), "r"(a[1]), "r"(a[2]), "r"(a[3]), "r"(b0), "r"(b1));
}
__device__ __forceinline__ void cpa16(uint32_t dst, const void* src) {
    asm volatile("cp.async.cg.shared.global [%0], [%1], 16;"
                 :: "r"(dst), "l"(src));
}
__device__ __forceinline__ void cpa_commit() {
    asm volatile("cp.async.commit_group;");
}

// ---------------------------------------------------------------------------
// Tensor-core input GEMM, 3-stage cp.async pipeline, occupancy pinned to 2.
// ---------------------------------------------------------------------------
#define ASTR  48
#define STAGE (4 * 128 * ASTR)   // 24576 B per stage

__global__ __launch_bounds__(256, 2) void gemm_pi_mma_k(const float* __restrict__ bi) {
    extern __shared__ char smg[];

    const int tid  = threadIdx.x;
    const int lane = tid & 31;
    const int warp = tid >> 5;
    const int wm   = warp >> 2;
    const int wn   = warp & 3;
    const int m0   = blockIdx.y * 128;
    const int n0   = blockIdx.x * 128;

    const int lrow  = tid >> 1;
    const int lhalf = tid & 1;
    const __nv_bfloat16* pxh = g_xhi + (size_t)(m0 + lrow) * D_ + lhalf * 8;
    const __nv_bfloat16* pxl = g_xlo + (size_t)(m0 + lrow) * D_ + lhalf * 8;
    const __nv_bfloat16* pwh = g_whi + (size_t)(n0 + lrow) * D_ + lhalf * 8;
    const __nv_bfloat16* pwl = g_wlo + (size_t)(n0 + lrow) * D_ + lhalf * 8;

    const uint32_t sbase = (uint32_t)__cvta_generic_to_shared(smg);
    const uint32_t stoff = lrow * ASTR + lhalf * 16;

    const int rowA = wm * 64 + (lane & 15);
    const uint32_t aAh0 = sbase + rowA * ASTR + (lane >> 4) * 16;
    const uint32_t aAl0 = aAh0 + 128 * ASTR;
    const int rowB = wn * 32 + (lane & 7) + ((lane >> 4) << 3);
    const uint32_t aBh0 = sbase + 2 * 128 * ASTR + rowB * ASTR + ((lane >> 3) & 1) * 16;
    const uint32_t aBl0 = aBh0 + 128 * ASTR;

    float acc[4][4][4];
#pragma unroll
    for (int i = 0; i < 4; i++)
#pragma unroll
        for (int j = 0; j < 4; j++)
#pragma unroll
            for (int e = 0; e < 4; e++) acc[i][j][e] = 0.f;

    auto commit_stage = [&](int p, int kts) {
        uint32_t d = sbase + p * STAGE + stoff;
        const int ko = kts * 16;
        cpa16(d,                  pxh + ko);
        cpa16(d + 128 * ASTR,     pxl + ko);
        cpa16(d + 2 * 128 * ASTR, pwh + ko);
        cpa16(d + 3 * 128 * ASTR, pwl + ko);
        cpa_commit();
    };

    commit_stage(0, 0);
    commit_stage(1, 1);

    for (int kts = 0; kts < 32; kts++) {
        if (kts < 31) asm volatile("cp.async.wait_group 1;");
        else          asm volatile("cp.async.wait_group 0;");
        __syncthreads();
        if (kts + 2 < 32) commit_stage((kts + 2) % 3, kts + 2);

        const uint32_t po = (kts % 3) * STAGE;

        uint32_t ah[4][4], al[4][4], bh[4][2], bl[4][2];
#pragma unroll
        for (int mi = 0; mi < 4; mi++) {
            ldsm_x4(ah[mi][0], ah[mi][1], ah[mi][2], ah[mi][3], aAh0 + po + mi * 16 * ASTR);
            ldsm_x4(al[mi][0], al[mi][1], al[mi][2], al[mi][3], aAl0 + po + mi * 16 * ASTR);
        }
#pragma unroll
        for (int bg = 0; bg < 2; bg++) {
            ldsm_x4(bh[2 * bg][0], bh[2 * bg][1], bh[2 * bg + 1][0], bh[2 * bg + 1][1],
                    aBh0 + po + bg * 16 * ASTR);
            ldsm_x4(bl[2 * bg][0], bl[2 * bg][1], bl[2 * bg + 1][0], bl[2 * bg + 1][1],
                    aBl0 + po + bg * 16 * ASTR);
        }
#pragma unroll
        for (int mi = 0; mi < 4; mi++)
#pragma unroll
            for (int ni = 0; ni < 4; ni++) {
                mma16816(acc[mi][ni], ah[mi], bh[ni][0], bh[ni][1]);
                mma16816(acc[mi][ni], ah[mi], bl[ni][0], bl[ni][1]);
                mma16816(acc[mi][ni], al[mi], bh[ni][0], bh[ni][1]);
            }
    }

#pragma unroll
    for (int ni = 0; ni < 4; ni++) {
        const int n = n0 + wn * 32 + ni * 8 + 2 * (lane & 3);
        float b0 = bi[n], b1 = bi[n + 1];
#pragma unroll
        for (int mi = 0; mi < 4; mi++) {
            const int m = m0 + wm * 64 + mi * 16 + (lane >> 2);
            float* C0 = g_pi + (size_t)m * SIXH + n;
            float* C1 = g_pi + (size_t)(m + 8) * SIXH + n;
            *(float2*)C0 = make_float2(acc[mi][ni][0] + b0, acc[mi][ni][1] + b1);
            *(float2*)C1 = make_float2(acc[mi][ni][2] + b0, acc[mi][ni][3] + b1);
        }
    }
}

// ---------------------------------------------------------------------------
// Persistent scan with per-k-chunk dataflow sync.
// Warp kh polls subgroup kh's arrival counter, then warp-locally copies its
// 64-column h chunk and runs its MMA — no block-wide barrier on that path.
// ---------------------------------------------------------------------------
__device__ __forceinline__ float sigm(float x)  { return 1.f / (1.f + __expf(-x)); }
__device__ __forceinline__ float tanh_(float x) { return 1.f - 2.f / (__expf(2.f * x) + 1.f); }

__global__ __launch_bounds__(NTHR, 1) void lstm_scan_k(
    const float* __restrict__ Ws, const float* __restrict__ bs,
    const int* __restrict__ lengths, float* __restrict__ out)
{
    extern __shared__ char smc[];
    __nv_bfloat16* sAh   = (__nv_bfloat16*)smc;          // 16 x SSTR
    __nv_bfloat16* sAl   = sAh + 16 * SSTR;              // 16 x SSTR
    __nv_bfloat16* sWh   = sAl + 16 * SSTR;              // NROW x SSTR
    __nv_bfloat16* sWl   = sWh + NROW * SSTR;            // NROW x SSTR
    float*         sPart = (float*)(sWl + NROW * SSTR);  // 8 x 16 x PSTR

    const int tid   = threadIdx.x;
    const int blk   = blockIdx.x;
    const int lane  = tid & 31;
    const int warp  = tid >> 5;
    const int group = blk >> 6;
    const int cb    = blk & 63;
    const int sub   = cb >> 3;

    // --- Ws -> smem bf16 split ---
    for (int i = tid; i < NROW * (H_ / 8); i += NTHR) {
        int l  = i >> 6;
        int d8 = (i & 63) << 3;
        __nv_bfloat16* ph = sWh + l * SSTR + d8;
        __nv_bfloat16* pl = sWl + l * SSTR + d8;
        int row = (l >> 3) * H_ + cb * CPB + (l & 7);
        const float* p = Ws + (size_t)row * H_ + d8;
#pragma unroll
        for (int q = 0; q < 8; q++) {
            float f = p[q];
            __nv_bfloat16 hh = __float2bfloat16(f);
            ph[q] = hh;
            pl[q] = __float2bfloat16(f - __bfloat162float(hh));
        }
    }

    // MMA addressing: warp = k-chunk kh (64 k-elems each)
    const int kh = warp;
    const uint32_t aAh = (uint32_t)__cvta_generic_to_shared(
        sAh + (size_t)(lane & 15) * SSTR) + (lane >> 4) * 16 + kh * 128;
    const uint32_t aAl = aAh + 16 * SSTR * 2;
    const uint32_t aBh = (uint32_t)__cvta_generic_to_shared(
        sWh + (size_t)(lane & 7) * SSTR) + ((lane >> 3) & 1) * 16 + kh * 128;
    const uint32_t aBl = aBh + NROW * SSTR * 2;

    // Gate threads: tid<128 owns (b_local = tid>>3, jj = tid&7)
    float c_reg = 0.f, h_reg = 0.f;
    float bsv[5] = {0.f, 0.f, 0.f, 0.f, 0.f};
    int bg = 0, j0 = 0, len = 0, b_local = 0;
    if (tid < 128) {
        b_local = tid >> 3;
        bg = group * BGRP + b_local;
        j0 = cb * CPB + (tid & 7);
        len = lengths[bg];
#pragma unroll
        for (int g = 0; g < 5; g++) bsv[g] = bs[g * H_ + j0];
        __stcg((unsigned short*)&g_hhi[bg * H_ + j0], (unsigned short)0);
        __stcg((unsigned short*)&g_hlo[bg * H_ + j0], (unsigned short)0);
        __threadfence();
    }
    __syncthreads();
    if (tid == 0) atomicAdd(&g_cnt[group][sub], 1u);   // h0 published

    const int hbase = group * BGRP * H_;
    const volatile unsigned* cptr = &g_cnt[group][kh];
    const uint32_t dh = (uint32_t)__cvta_generic_to_shared(sAh);
    const uint32_t dl = (uint32_t)__cvta_generic_to_shared(sAl);

    // Deep pi prefetch
    float pv_cur[6] = {0,0,0,0,0,0}, pv_nxt[6] = {0,0,0,0,0,0};
    const float* ppi = (tid < 128) ? g_pi + (size_t)bg * T_ * SIXH + j0 : g_pi;
    if (tid < 128) {
#pragma unroll
        for (int g = 0; g < 6; g++) pv_cur[g] = __ldg(ppi + g * H_);
    }

    for (int t = 0; t < T_; t++) {
        // next step's pi loads (overlap the poll)
        if (tid < 128 && t + 1 < T_) {
            const float* pp = ppi + (size_t)(t + 1) * SIXH;
#pragma unroll
            for (int g = 0; g < 6; g++) pv_nxt[g] = __ldg(pp + g * H_);
        }

        // poll my chunk's writers (subgroup kh of my group)
        if (lane == 0) {
            while (*cptr < 8u * (unsigned)(t + 1)) {}
        }
        __syncwarp();

        // warp-local copy of chunk kh: 16 rows x 64 cols, hi+lo
        {
            const char* ph = (const char*)(g_hhi + (t & 1) * BH + hbase);
            const char* pl = (const char*)(g_hlo + (t & 1) * BH + hbase);
#pragma unroll
            for (int i = lane; i < 128; i += 32) {
                int r  = i >> 3;
                int cc = ((i & 7) << 3) + kh * 64;
                cpa16(dh + (r * SSTR + cc) * 2, ph + (r * H_ + cc) * 2);
                cpa16(dl + (r * SSTR + cc) * 2, pl + (r * H_ + cc) * 2);
            }
            cpa_commit();
            asm volatile("cp.async.wait_group 0;");
            __syncwarp();
        }

        // MMA: 16x40 partial over k-chunk [kh*64, kh*64+64)
        {
            float acc[5][4];
#pragma unroll
            for (int ni = 0; ni < 5; ni++)
#pragma unroll
                for (int e = 0; e < 4; e++) acc[ni][e] = 0.f;
#pragma unroll
            for (int kk = 0; kk < 4; kk++) {
                const uint32_t ko = kk * 32;
                uint32_t ah[4], al[4];
                ldsm_x4(ah[0], ah[1], ah[2], ah[3], aAh + ko);
                ldsm_x4(al[0], al[1], al[2], al[3], aAl + ko);
#pragma unroll
                for (int ni = 0; ni < 5; ni++) {
                    const uint32_t bo = ko + ni * 8 * SSTR * 2;
                    uint32_t b0h, b1h, b0l, b1l;
                    ldsm_x2(b0h, b1h, aBh + bo);
                    ldsm_x2(b0l, b1l, aBl + bo);
                    mma16816(acc[ni], ah, b0h, b1h);
                    mma16816(acc[ni], al, b0h, b1h);
                    mma16816(acc[ni], ah, b0l, b1l);
                }
            }
            float* pp = sPart + kh * 16 * PSTR;
            const int r = lane >> 2;
#pragma unroll
            for (int ni = 0; ni < 5; ni++) {
                const int n = ni * 8 + 2 * (lane & 3);
                *(float2*)&pp[r * PSTR + n]       = make_float2(acc[ni][0], acc[ni][1]);
                *(float2*)&pp[(r + 8) * PSTR + n] = make_float2(acc[ni][2], acc[ni][3]);
            }
        }
        __syncthreads();   // partials ready

        // Gate phase
        if (tid < 128) {
            const int jj = tid & 7;
            float ps[5];
#pragma unroll
            for (int g = 0; g < 5; g++) {
                float s = 0.f;
#pragma unroll
                for (int w = 0; w < 8; w++)
                    s += sPart[w * 16 * PSTR + b_local * PSTR + g * 8 + jj];
                ps[g] = s + bsv[g];
            }
            float iv = sigm(pv_cur[0] + ps[0]);
            float fv = sigm(pv_cur[1] + ps[1]);
            float gv = tanh_(pv_cur[2] + ps[2]);
            float ov = sigm(pv_cur[3] + ps[3]);
            float cn = iv * gv + fv * c_reg;
            float o1 = ov * tanh_(cn);
            float rv = sigm(pv_cur[4] + ps[4]);
            float o2 = rv * o1 + (1.f - rv) * pv_cur[5];
            bool  m  = (t < len);
            h_reg = m ? o2 : h_reg;
            c_reg = m ? cn : c_reg;
            __nv_bfloat16 hh = __float2bfloat16(h_reg);
            __nv_bfloat16 hl = __float2bfloat16(h_reg - __bfloat162float(hh));
            const int idx = ((t + 1) & 1) * BH + bg * H_ + j0;
            __stcg((unsigned short*)&g_hhi[idx], __bfloat16_as_ushort(hh));
            __stcg((unsigned short*)&g_hlo[idx], __bfloat16_as_ushort(hl));
            out[((size_t)bg * T_ + t) * H_ + j0] = m ? o2 : 0.f;
            if (t == T_ - 1) {
                out[(size_t)B_ * T_ * H_ + bg * H_ + j0]      = h_reg;
                out[(size_t)B_ * T_ * H_ + BH + bg * H_ + j0] = c_reg;
            }
            __threadfence();   // publish h before arrival
        }
#pragma unroll
        for (int g = 0; g < 6; g++) pv_cur[g] = pv_nxt[g];

        __syncthreads();       // gates done, sPart consumable, h published
        if (tid == 0) atomicAdd(&g_cnt[group][sub], 1u);
    }
}

// ---------------------------------------------------------------------------
extern "C" void kernel_launch(void* const* d_in, const int* in_sizes, int n_in,
                              void* d_out, int out_size) {
    const float* x       = (const float*)d_in[0];
    const int*   lengths = (const int*)  d_in[1];
    const float* Wi      = (const float*)d_in[2];
    const float* bi      = (const float*)d_in[3];
    const float* Ws      = (const float*)d_in[4];
    const float* bs      = (const float*)d_in[5];
    float* out = (float*)d_out;

    const int smem_scan = (16 + 16 + NROW + NROW) * SSTR * 2 + 8 * 16 * PSTR * 4; // 139,008 B
    const int smem_gemm = 3 * STAGE;
    cudaFuncSetAttribute(lstm_scan_k,   cudaFuncAttributeMaxDynamicSharedMemorySize, smem_scan);
    cudaFuncSetAttribute(gemm_pi_mma_k, cudaFuncAttributeMaxDynamicSharedMemorySize, smem_gemm);

    init_k<<<1, 1>>>();

    __nv_bfloat16 *xhi, *xlo, *whi, *wlo;
    cudaGetSymbolAddress((void**)&xhi, g_xhi);
    cudaGetSymbolAddress((void**)&xlo, g_xlo);
    cudaGetSymbolAddress((void**)&whi, g_whi);
    cudaGetSymbolAddress((void**)&wlo, g_wlo);

    int nx4 = (B_ * T_ * D_) / 4;
    int nw4 = (SIXH * D_) / 4;
    split_k<<<(nx4 + 255) / 256, 256>>>(x, xhi, xlo, nx4);
    split_k<<<(nw4 + 255) / 256, 256>>>(Wi, whi, wlo, nw4);

    gemm_pi_mma_k<<<dim3(SIXH / 128, (B_ * T_) / 128), 256, smem_gemm>>>(bi);
    lstm_scan_k<<<NBLK, NTHR, smem_scan>>>(Ws, bs, lengths, out);
}